// round 8
// baseline (speedup 1.0000x reference)
#include <cuda_runtime.h>
#include <cuda_fp16.h>
#include <cstdint>
#include <cstddef>

#define B_ 4
#define T_ 512
#define H_ 128
#define D_ 300
#define V_ 50257
#define E_ 64

// ---------------- static device scratch ----------------
__device__ float  g_xwp [T_*H_*16];         // gates pre-act, layout [t][dim][batch][gate]
__device__ float  g_h   [B_*T_*H_];         // LSTM hidden states
__device__ float  g_weh [B_*T_*H_];         // We @ h
__device__ float  g_wdh [B_*T_*H_];         // Wd @ h
__device__ float  g_hh  [B_*T_];            // ||h||^2
__device__ float  g_fsrc[B_*T_*H_];         // selected feature source vector
__device__ int    g_sel [B_*T_];            // eid > 0 flag
__device__ __half g_z16 [B_*T_*H_];         // z = h + ent_feat (fp16)
__device__ __half g_wx16[(size_t)V_*H_];    // Wx in fp16

__device__ __forceinline__ uint32_t pack_h2(float a, float b) {
    __half2 h = __floats2half2_rn(a, b);
    return *reinterpret_cast<uint32_t*>(&h);
}
__device__ __forceinline__ float tanh_fast(float x) {
    float y;
    asm("tanh.approx.f32 %0, %1;" : "=f"(y) : "f"(x));
    return y;
}
__device__ __forceinline__ float sigmoid_fast(float x) {
    return 0.5f * tanh_fast(0.5f * x) + 0.5f;
}

// ---------------- K0: Wx -> fp16 (split into two launches for ncu indexing) ----------------
__global__ void k_cvt(const float* __restrict__ src, __half* __restrict__ dst,
                      int off, int n) {
    int i = off + blockIdx.x * blockDim.x + threadIdx.x;
    if (i < n) dst[i] = __float2half(src[i]);
}

// ---------------- K1: xw = embed[tok] @ Wih^T + bih + bhh, permuted layout ----------------
__global__ void k_xw(const int* __restrict__ tokens, const float* __restrict__ embed,
                     const float* __restrict__ Wih, const float* __restrict__ bih,
                     const float* __restrict__ bhh) {
    __shared__ __align__(16) float xs[16][D_];
    int b = blockIdx.y, t0 = blockIdx.x * 16, n = threadIdx.x;
    for (int i = n; i < 16 * D_; i += 512) {
        int r = i / D_, d = i - r * D_;
        xs[r][d] = embed[(size_t)tokens[b * T_ + t0 + r] * D_ + d];
    }
    __syncthreads();
    float acc[16];
#pragma unroll
    for (int r = 0; r < 16; r++) acc[r] = 0.f;
    const float4* wr = reinterpret_cast<const float4*>(Wih + (size_t)n * D_);
#pragma unroll 5
    for (int d4 = 0; d4 < D_ / 4; d4++) {
        float4 w = __ldg(wr + d4);
#pragma unroll
        for (int r = 0; r < 16; r++) {
            float4 x = *reinterpret_cast<const float4*>(&xs[r][d4 * 4]);
            acc[r] += w.x * x.x + w.y * x.y + w.z * x.z + w.w * x.w;
        }
    }
    float bb = bih[n] + bhh[n];
    int gate = n >> 7, dd = n & 127;
    for (int r = 0; r < 16; r++)
        g_xwp[(((size_t)(t0 + r) * H_ + dd) << 4) + b * 4 + gate] = acc[r] + bb;
}

// ---------------- K2: sequential LSTM, gate-permuted, 1 barrier/step ----------------
// even/odd ks accumulator split: dependent HMMA chain depth 8 -> 4
__global__ void __launch_bounds__(512, 1) k_lstm4(const float* __restrict__ Whh) {
    __shared__ __half2 hbuf[2][4][72];
    int tid = threadIdx.x, wid = tid >> 5, lane = tid & 31;

    uint32_t afr[2][8][4];
#pragma unroll
    for (int m = 0; m < 2; m++)
#pragma unroll
        for (int ks = 0; ks < 8; ks++) {
            int rl = (m ? 256 : 0) + 8 * wid + (lane >> 2);
            int rh = rl + 128;
            int k0 = 16 * ks + (lane & 3) * 2;
            float2 wl0 = __ldg(reinterpret_cast<const float2*>(Whh + (size_t)rl * H_ + k0));
            float2 wh0 = __ldg(reinterpret_cast<const float2*>(Whh + (size_t)rh * H_ + k0));
            float2 wl8 = __ldg(reinterpret_cast<const float2*>(Whh + (size_t)rl * H_ + k0 + 8));
            float2 wh8 = __ldg(reinterpret_cast<const float2*>(Whh + (size_t)rh * H_ + k0 + 8));
            afr[m][ks][0] = pack_h2(wl0.x, wl0.y);
            afr[m][ks][1] = pack_h2(wh0.x, wh0.y);
            afr[m][ks][2] = pack_h2(wl8.x, wl8.y);
            afr[m][ks][3] = pack_h2(wh8.x, wh8.y);
        }

    if (tid < 288) {
        __half2 z = __half2half2(__float2half(0.f));
        (&hbuf[0][0][0])[tid] = z;
    }
    int bq = lane & 3;
    int hd = 8 * wid + (lane >> 2);
    int myb = ((bq & 1) << 1) | (bq >> 1);
    int sel = bq >> 1;
    int bb = (lane >> 2) & 3;
    int kq = lane & 3;
    int i0 = sel ? 1 : 0;       // accumulator index for gates i,g
    int i1 = sel ? 3 : 2;       // accumulator index for gates f,o
    float c = 0.f;
    __syncthreads();

    const float4* xwp4 = reinterpret_cast<const float4*>(g_xwp);
    float4 xa = __ldg(&xwp4[(size_t)hd * 4 + myb]);

    for (int t = 0; t < T_; t++) {
        int buf = t & 1;
        float a0e[4] = {0.f, 0.f, 0.f, 0.f};
        float a0o[4] = {0.f, 0.f, 0.f, 0.f};
        float a1e[4] = {0.f, 0.f, 0.f, 0.f};
        float a1o[4] = {0.f, 0.f, 0.f, 0.f};
#pragma unroll
        for (int kp = 0; kp < 4; kp++) {
            int kse = kp * 2, kso = kp * 2 + 1;
            uint32_t be0 = *reinterpret_cast<const uint32_t*>(&hbuf[buf][bb][kse * 8 + kq]);
            uint32_t be1 = *reinterpret_cast<const uint32_t*>(&hbuf[buf][bb][kse * 8 + kq + 4]);
            uint32_t bo0 = *reinterpret_cast<const uint32_t*>(&hbuf[buf][bb][kso * 8 + kq]);
            uint32_t bo1 = *reinterpret_cast<const uint32_t*>(&hbuf[buf][bb][kso * 8 + kq + 4]);
            asm volatile(
                "mma.sync.aligned.m16n8k16.row.col.f32.f16.f16.f32 "
                "{%0,%1,%2,%3}, {%4,%5,%6,%7}, {%8,%9}, {%0,%1,%2,%3};"
                : "+f"(a0e[0]), "+f"(a0e[1]), "+f"(a0e[2]), "+f"(a0e[3])
                : "r"(afr[0][kse][0]), "r"(afr[0][kse][1]),
                  "r"(afr[0][kse][2]), "r"(afr[0][kse][3]),
                  "r"(be0), "r"(be1));
            asm volatile(
                "mma.sync.aligned.m16n8k16.row.col.f32.f16.f16.f32 "
                "{%0,%1,%2,%3}, {%4,%5,%6,%7}, {%8,%9}, {%0,%1,%2,%3};"
                : "+f"(a0o[0]), "+f"(a0o[1]), "+f"(a0o[2]), "+f"(a0o[3])
                : "r"(afr[0][kso][0]), "r"(afr[0][kso][1]),
                  "r"(afr[0][kso][2]), "r"(afr[0][kso][3]),
                  "r"(bo0), "r"(bo1));
            asm volatile(
                "mma.sync.aligned.m16n8k16.row.col.f32.f16.f16.f32 "
                "{%0,%1,%2,%3}, {%4,%5,%6,%7}, {%8,%9}, {%0,%1,%2,%3};"
                : "+f"(a1e[0]), "+f"(a1e[1]), "+f"(a1e[2]), "+f"(a1e[3])
                : "r"(afr[1][kse][0]), "r"(afr[1][kse][1]),
                  "r"(afr[1][kse][2]), "r"(afr[1][kse][3]),
                  "r"(be0), "r"(be1));
            asm volatile(
                "mma.sync.aligned.m16n8k16.row.col.f32.f16.f16.f32 "
                "{%0,%1,%2,%3}, {%4,%5,%6,%7}, {%8,%9}, {%0,%1,%2,%3};"
                : "+f"(a1o[0]), "+f"(a1o[1]), "+f"(a1o[2]), "+f"(a1o[3])
                : "r"(afr[1][kso][0]), "r"(afr[1][kso][1]),
                  "r"(afr[1][kso][2]), "r"(afr[1][kso][3]),
                  "r"(bo0), "r"(bo1));
        }
        float4 xn = make_float4(0.f, 0.f, 0.f, 0.f);
        if (t + 1 < T_)
            xn = __ldg(&xwp4[((size_t)(t + 1) * H_ + hd) * 4 + myb]);

        float gi = a0e[i0] + a0o[i0] + xa.x;
        float gf = a0e[i1] + a0o[i1] + xa.y;
        float gg = a1e[i0] + a1o[i0] + xa.z;
        float go = a1e[i1] + a1o[i1] + xa.w;
        float si = sigmoid_fast(gi);
        float sf = sigmoid_fast(gf);
        float so = sigmoid_fast(go);
        c = sf * c + si * tanh_fast(gg);
        float h = so * tanh_fast(c);
        g_h[(size_t)(myb * T_ + t) * H_ + hd] = h;
        reinterpret_cast<__half*>(&hbuf[buf ^ 1][myb][0])[hd] = __float2half(h);
        __syncthreads();
        xa = xn;
    }
}

// ---------------- K3: veh = We@h, vdh = Wd@h, + pred_r + ||h||^2 ----------------
__global__ void k_vw(const float* __restrict__ We, const float* __restrict__ Wd,
                     const float* __restrict__ Wr, const float* __restrict__ br,
                     float* __restrict__ out_pr) {
    __shared__ __align__(16) float hsm[16][H_];
    __shared__ float wr_s[H_];
    int row0 = blockIdx.x * 16;
    int tid = threadIdx.x;
    for (int i = tid; i < 16 * H_; i += 256)
        hsm[i >> 7][i & 127] = g_h[(size_t)row0 * H_ + i];
    if (tid < H_) wr_s[tid] = Wr[tid];
    __syncthreads();
    int k = tid & 127;
    const float* M = (tid < 128) ? We : Wd;
    float* O = (tid < 128) ? g_weh : g_wdh;
    const float4* mrow = reinterpret_cast<const float4*>(M + (size_t)k * H_);
    float acc[16];
#pragma unroll
    for (int r = 0; r < 16; r++) acc[r] = 0.f;
#pragma unroll 4
    for (int k4 = 0; k4 < H_ / 4; k4++) {
        float4 w = __ldg(mrow + k4);
#pragma unroll
        for (int r = 0; r < 16; r++) {
            float4 h = *reinterpret_cast<const float4*>(&hsm[r][k4 * 4]);
            acc[r] += w.x * h.x + w.y * h.y + w.z * h.z + w.w * h.w;
        }
    }
    for (int r = 0; r < 16; r++)
        O[(size_t)(row0 + r) * H_ + k] = acc[r];

    int warp = tid >> 5, lane = tid & 31;
    float brv = __ldg(br);
#pragma unroll
    for (int rr = 0; rr < 2; rr++) {
        int r = warp * 2 + rr;
        float h0 = hsm[r][lane],      h1 = hsm[r][lane + 32];
        float h2 = hsm[r][lane + 64], h3 = hsm[r][lane + 96];
        float p = h0 * wr_s[lane]      + h1 * wr_s[lane + 32]
                + h2 * wr_s[lane + 64] + h3 * wr_s[lane + 96];
        float s = h0 * h0 + h1 * h1 + h2 * h2 + h3 * h3;
#pragma unroll
        for (int o = 16; o; o >>= 1) {
            p += __shfl_down_sync(0xffffffffu, p, o);
            s += __shfl_down_sync(0xffffffffu, s, o);
        }
        if (lane == 0) {
            out_pr[row0 + r] = 1.f / (1.f + __expf(-(p + brv)));
            g_hh[row0 + r] = s;
        }
    }
}

// ---------------- K4: sequential entity recurrence, 2 barriers/step ----------------
// vdh/h dots use prefetched registers directly (no SMEM staging for vdh, h-dot).
__global__ void k_ent2(const int* __restrict__ eids, const int* __restrict__ sids,
                       const float* __restrict__ ents0, const float* __restrict__ lamp,
                       float* __restrict__ out_pe) {
    __shared__ float entsT[H_][E_ + 1];
    __shared__ float dists[E_];
    __shared__ float veh_s[H_], h_s[H_], last_s[H_];
    __shared__ float red2[256];
    __shared__ float nred[4];    // ent . vdh partials
    __shared__ float nred2[4];   // ent . h partials
    int b = blockIdx.x, tid = threadIdx.x;
    float lam = *lamp;
    for (int i = tid; i < E_ * H_; i += 256) {
        int e = i >> 7, j = i & 127;
        entsT[j][e] = ents0[(size_t)(b * E_ + e) * H_ + j];
    }
    if (tid < E_) dists[tid] = 0.f;
    if (tid < H_) last_s[tid] = ents0[(size_t)b * E_ * H_ + tid];
    __syncthreads();
    int q = tid >> 6, e = tid & 63;
    int lane = tid & 31, warp = tid >> 5;
    int jd = tid & 127;   // dim for dot duty

    // prefetch t=0: all threads carry h[jd]; tid<128 also carry veh/vdh
    float pv = 0.f, pd = 0.f;
    float ph;
    {
        size_t bt0 = (size_t)b * T_ * H_;
        if (tid < H_) {
            pv = __ldg(&g_weh[bt0 + tid]);
            pd = __ldg(&g_wdh[bt0 + tid]);
        }
        ph = __ldg(&g_h[bt0 + jd]);
    }
    int peid = __ldg(&eids[b * T_]);
    float psid = (float)__ldg(&sids[b * T_]);
    float phh = __ldg(&g_hh[b * T_]);

    for (int t = 0; t < T_; t++) {
        int bt = b * T_ + t;
        if (tid < H_) { veh_s[tid] = pv; h_s[tid] = ph; }
        int eid = peid;
        float sid = psid;
        float hh = phh;
        float vd = pd;     // own vdh value (dim jd), register
        float hv = ph;     // own h value (dim jd), register
        __syncthreads();  // S1: staging + prev-step updates visible
        // prefetch t+1
        if (t + 1 < T_) {
            size_t bt1 = (size_t)(bt + 1) * H_;
            if (tid < H_) {
                pv = __ldg(&g_weh[bt1 + tid]);
                pd = __ldg(&g_wdh[bt1 + tid]);
            }
            ph = __ldg(&g_h[bt1 + jd]);
            peid = __ldg(&eids[bt + 1]);
            psid = (float)__ldg(&sids[bt + 1]);
            phh = __ldg(&g_hh[bt + 1]);
        }
        // phase 1: exp term (reads pre-update dists)
        float expterm = 0.f;
        if (tid < E_) expterm = expf((dists[tid] - sid) * lam);
        // pred_e partials: thread (q,e), 4 accumulators
        float p0 = 0.f, p1 = 0.f, p2 = 0.f, p3 = 0.f;
#pragma unroll
        for (int jj = 0; jj < 8; jj++) {
            int j = q * 32 + jj * 4;
            p0 += entsT[j][e]     * veh_s[j];
            p1 += entsT[j + 1][e] * veh_s[j + 1];
            p2 += entsT[j + 2][e] * veh_s[j + 2];
            p3 += entsT[j + 3][e] * veh_s[j + 3];
        }
        red2[tid] = (p0 + p1) + (p2 + p3);
        // dual dots from registers: warps 0-3 ent.vdh, warps 4-7 ent.h
        float ent_val = entsT[jd][eid];
        float d = ent_val * ((tid < 128) ? vd : hv);
#pragma unroll
        for (int o = 16; o; o >>= 1) d += __shfl_down_sync(0xffffffffu, d, o);
        if (lane == 0) {
            if (warp < 4) nred[warp] = d;
            else          nred2[warp - 4] = d;
        }
        __syncthreads();  // S2
        // phase 2
        if (tid < E_) {
            out_pe[(size_t)bt * E_ + tid] =
                red2[tid] + red2[tid + 64] + red2[tid + 128] + red2[tid + 192] + expterm;
        }
        float dotdv = nred[0] + nred[1] + nred[2] + nred[3];
        float doteh = nred2[0] + nred2[1] + nred2[2] + nred2[3];
        float delta = 1.f / (1.f + __expf(-dotdv));
        float omd = 1.f - delta;
        float n2 = delta * delta + 2.f * delta * omd * doteh + omd * omd * hh;
        float rn = rsqrtf(n2);
        if (tid < H_) {
            float u = delta * ent_val + omd * h_s[tid];
            float un = u * rn;
            float fs = (eid > 0) ? un : last_s[tid];
            g_fsrc[(size_t)bt * H_ + tid] = fs;
            entsT[tid][eid] = un;
            last_s[tid] = un;
        }
        if (tid == 0) { dists[eid] = sid; g_sel[bt] = (eid > 0) ? 1 : 0; }
        // next S1 orders these writes before next reads
    }
}

// ---------------- K5: ent_feat + z (fp16) ----------------
__global__ void k_feat(const float* __restrict__ WTe, const float* __restrict__ WTc) {
    __shared__ __align__(16) float fs[8][H_];
    int row0 = blockIdx.x * 8;
    int j = threadIdx.x;
    for (int i = j; i < 8 * H_; i += 128)
        fs[i >> 7][i & 127] = g_fsrc[(size_t)row0 * H_ + i];
    __syncthreads();
    float acc_e[8], acc_c[8];
#pragma unroll
    for (int r = 0; r < 8; r++) { acc_e[r] = 0.f; acc_c[r] = 0.f; }
    const float4* we4 = reinterpret_cast<const float4*>(WTe + (size_t)j * H_);
    const float4* wc4 = reinterpret_cast<const float4*>(WTc + (size_t)j * H_);
#pragma unroll 4
    for (int k4 = 0; k4 < H_ / 4; k4++) {
        float4 we = __ldg(we4 + k4);
        float4 wc = __ldg(wc4 + k4);
#pragma unroll
        for (int r = 0; r < 8; r++) {
            float4 f = *reinterpret_cast<const float4*>(&fs[r][k4 * 4]);
            acc_e[r] += we.x * f.x + we.y * f.y + we.z * f.z + we.w * f.w;
            acc_c[r] += wc.x * f.x + wc.y * f.y + wc.z * f.z + wc.w * f.w;
        }
    }
    for (int r = 0; r < 8; r++) {
        int bt = row0 + r;
        float feat = g_sel[bt] ? acc_e[r] : acc_c[r];
        float z = g_h[(size_t)bt * H_ + j] + feat;
        g_z16[(size_t)bt * H_ + j] = __float2half(z);
    }
}

// ---------------- K6: logits = z @ Wx^T + bx, 128x128 tiles ----------------
__global__ void __launch_bounds__(256, 2) k_logits(const float* __restrict__ bx,
                                                   float* __restrict__ out) {
    extern __shared__ __align__(16) __half smemh[];
    __half (*sA)[128] = reinterpret_cast<__half (*)[128]>(smemh);
    __half (*sB)[128] = reinterpret_cast<__half (*)[128]>(smemh + 128 * 128);
    int tid = threadIdx.x;
    int m0 = blockIdx.y * 128;
    int n0 = blockIdx.x * 128;
    {
        int r = tid >> 1;
        int cbase = (tid & 1) * 8;
        const uint4* src = reinterpret_cast<const uint4*>(g_z16) + (size_t)(m0 + r) * 16;
#pragma unroll
        for (int i = 0; i < 8; i++) {
            int c = cbase + i;
            uint4 v = src[c];
            *reinterpret_cast<uint4*>(&sA[r][(c ^ (r & 7)) << 3]) = v;
        }
    }
    {
        int r = tid >> 1;
        int cbase = (tid & 1) * 8;
        int v_ = n0 + r;
        const uint4* src = reinterpret_cast<const uint4*>(g_wx16) + (size_t)v_ * 16;
#pragma unroll
        for (int i = 0; i < 8; i++) {
            int c = cbase + i;
            uint4 v;
            if (v_ < V_) v = src[c];
            else { v.x = 0u; v.y = 0u; v.z = 0u; v.w = 0u; }
            *reinterpret_cast<uint4*>(&sB[r][(c ^ (r & 7)) << 3]) = v;
        }
    }
    __syncthreads();

    int lane = tid & 31, warp = tid >> 5;
    int wm = warp >> 1, wn = warp & 1;
    float acc[2][8][4];
#pragma unroll
    for (int mt = 0; mt < 2; mt++)
#pragma unroll
        for (int nt = 0; nt < 8; nt++)
#pragma unroll
            for (int i = 0; i < 4; i++) acc[mt][nt][i] = 0.f;

#pragma unroll
    for (int ks = 0; ks < 8; ks++) {
        uint32_t afrag[2][4];
#pragma unroll
        for (int mt = 0; mt < 2; mt++) {
            int row = wm * 32 + mt * 16 + (lane & 15);
            int chunk = ks * 2 + (lane >> 4);
            unsigned addr = (unsigned)__cvta_generic_to_shared(&sA[row][(chunk ^ (row & 7)) << 3]);
            asm volatile("ldmatrix.sync.aligned.m8n8.x4.shared.b16 {%0,%1,%2,%3}, [%4];"
                         : "=r"(afrag[mt][0]), "=r"(afrag[mt][1]),
                           "=r"(afrag[mt][2]), "=r"(afrag[mt][3]) : "r"(addr));
        }
        uint32_t bfrag[8][2];
#pragma unroll
        for (int nt = 0; nt < 8; nt++) {
            int row = wn * 64 + nt * 8 + (lane & 7);
            int chunk = ks * 2 + ((lane >> 3) & 1);
            unsigned addr = (unsigned)__cvta_generic_to_shared(&sB[row][(chunk ^ (row & 7)) << 3]);
            asm volatile("ldmatrix.sync.aligned.m8n8.x2.shared.b16 {%0,%1}, [%2];"
                         : "=r"(bfrag[nt][0]), "=r"(bfrag[nt][1]) : "r"(addr));
        }
#pragma unroll
        for (int mt = 0; mt < 2; mt++)
#pragma unroll
            for (int nt = 0; nt < 8; nt++) {
                asm volatile(
                    "mma.sync.aligned.m16n8k16.row.col.f32.f16.f16.f32 "
                    "{%0,%1,%2,%3}, {%4,%5,%6,%7}, {%8,%9}, {%0,%1,%2,%3};"
                    : "+f"(acc[mt][nt][0]), "+f"(acc[mt][nt][1]),
                      "+f"(acc[mt][nt][2]), "+f"(acc[mt][nt][3])
                    : "r"(afrag[mt][0]), "r"(afrag[mt][1]),
                      "r"(afrag[mt][2]), "r"(afrag[mt][3]),
                      "r"(bfrag[nt][0]), "r"(bfrag[nt][1]));
            }
    }
    int rrow = lane >> 2, col = (lane & 3) * 2;
#pragma unroll
    for (int mt = 0; mt < 2; mt++) {
#pragma unroll
        for (int nt = 0; nt < 8; nt++) {
            size_t gm = (size_t)(m0 + wm * 32 + mt * 16 + rrow);
            int gv = n0 + wn * 64 + nt * 8 + col;
            float* a = acc[mt][nt];
            if (gv < V_) {
                float b0 = bx[gv];
                out[gm * V_ + gv]       = a[0] + b0;
                out[(gm + 8) * V_ + gv] = a[2] + b0;
            }
            if (gv + 1 < V_) {
                float b1 = bx[gv + 1];
                out[gm * V_ + gv + 1]       = a[1] + b1;
                out[(gm + 8) * V_ + gv + 1] = a[3] + b1;
            }
        }
    }
}

// ---------------- launch ----------------
extern "C" void kernel_launch(void* const* d_in, const int* in_sizes, int n_in,
                              void* d_out, int out_size) {
    const int*   tokens = (const int*)d_in[0];
    const int*   eids   = (const int*)d_in[1];
    const int*   sids   = (const int*)d_in[2];
    const float* embed  = (const float*)d_in[3];
    const float* Wih    = (const float*)d_in[4];
    const float* Whh    = (const float*)d_in[5];
    const float* bih    = (const float*)d_in[6];
    const float* bhh    = (const float*)d_in[7];
    const float* Wr     = (const float*)d_in[8];
    const float* br     = (const float*)d_in[9];
    const float* We     = (const float*)d_in[10];
    const float* Wd     = (const float*)d_in[11];
    const float* WTe    = (const float*)d_in[12];
    const float* WTc    = (const float*)d_in[13];
    const float* Wx     = (const float*)d_in[14];
    const float* bx     = (const float*)d_in[15];
    const float* ents0  = (const float*)d_in[16];
    const float* lam    = (const float*)d_in[17];
    float* out = (float*)d_out;

    const size_t OFF_R = (size_t)B_ * T_ * V_;
    const size_t OFF_E = OFF_R + (size_t)B_ * T_;

    __half* wx16;
    cudaGetSymbolAddress((void**)&wx16, g_wx16);

    static int attr_set = 0;
    if (!attr_set) {
        cudaFuncSetAttribute(k_logits, cudaFuncAttributeMaxDynamicSharedMemorySize, 65536);
        attr_set = 1;
    }

    int nwx = V_ * H_;
    int half1 = (nwx / 2 + 255) & ~255;
    // launch order chosen so k_lstm4 sits at ncu's captured launch index (3)
    k_cvt<<<(half1 + 255) / 256, 256>>>(Wx, wx16, 0, half1);          // 0
    k_cvt<<<(nwx - half1 + 255) / 256, 256>>>(Wx, wx16, half1, nwx);  // 1
    k_xw<<<dim3(T_ / 16, B_), 512>>>(tokens, embed, Wih, bih, bhh);   // 2
    k_lstm4<<<1, 512>>>(Whh);                                         // 3  <- profiled
    k_vw<<<(B_ * T_) / 16, 256>>>(We, Wd, Wr, br, out + OFF_R);       // 4
    k_ent2<<<B_, 256>>>(eids, sids, ents0, lam, out + OFF_E);         // 5
    k_feat<<<(B_ * T_) / 8, 128>>>(WTe, WTc);                         // 6
    k_logits<<<dim3((V_ + 127) / 128, (B_ * T_) / 128), 256, 65536>>>(bx, out);  // 7
}

// round 9
// speedup vs baseline: 1.3230x; 1.3230x over previous
#include <cuda_runtime.h>
#include <cuda_fp16.h>
#include <cstdint>
#include <cstddef>

#define B_ 4
#define T_ 512
#define H_ 128
#define D_ 300
#define V_ 50257
#define E_ 64

// ---------------- static device scratch ----------------
__device__ float  g_xwp [T_*H_*16];         // gates pre-act, layout [t][dim][batch][gate]
__device__ float  g_h   [B_*T_*H_];         // LSTM hidden states
__device__ float  g_weh [B_*T_*H_];         // We @ h
__device__ float  g_wdh [B_*T_*H_];         // Wd @ h
__device__ float  g_hh  [B_*T_];            // ||h||^2
__device__ float  g_fsrc[B_*T_*H_];         // selected feature source vector
__device__ int    g_sel [B_*T_];            // eid > 0 flag
__device__ __half g_z16 [B_*T_*H_];         // z = h + ent_feat (fp16)
__device__ __half g_wx16[(size_t)V_*H_];    // Wx in fp16

__device__ __forceinline__ uint32_t pack_h2(float a, float b) {
    __half2 h = __floats2half2_rn(a, b);
    return *reinterpret_cast<uint32_t*>(&h);
}
__device__ __forceinline__ float tanh_fast(float x) {
    float y;
    asm("tanh.approx.f32 %0, %1;" : "=f"(y) : "f"(x));
    return y;
}
__device__ __forceinline__ float sigmoid_fast(float x) {
    return 0.5f * tanh_fast(0.5f * x) + 0.5f;
}

// ---------------- K0: Wx -> fp16 ----------------
__global__ void k_cvt(const float* __restrict__ src, __half* __restrict__ dst, int n) {
    int i = blockIdx.x * blockDim.x + threadIdx.x;
    if (i < n) dst[i] = __float2half(src[i]);
}

// ---------------- K1: xw = embed[tok] @ Wih^T + bih + bhh, permuted layout ----------------
__global__ void k_xw(const int* __restrict__ tokens, const float* __restrict__ embed,
                     const float* __restrict__ Wih, const float* __restrict__ bih,
                     const float* __restrict__ bhh) {
    __shared__ __align__(16) float xs[16][D_];
    int b = blockIdx.y, t0 = blockIdx.x * 16, n = threadIdx.x;
    for (int i = n; i < 16 * D_; i += 512) {
        int r = i / D_, d = i - r * D_;
        xs[r][d] = embed[(size_t)tokens[b * T_ + t0 + r] * D_ + d];
    }
    __syncthreads();
    float acc[16];
#pragma unroll
    for (int r = 0; r < 16; r++) acc[r] = 0.f;
    const float4* wr = reinterpret_cast<const float4*>(Wih + (size_t)n * D_);
#pragma unroll 5
    for (int d4 = 0; d4 < D_ / 4; d4++) {
        float4 w = __ldg(wr + d4);
#pragma unroll
        for (int r = 0; r < 16; r++) {
            float4 x = *reinterpret_cast<const float4*>(&xs[r][d4 * 4]);
            acc[r] += w.x * x.x + w.y * x.y + w.z * x.z + w.w * x.w;
        }
    }
    float bb = bih[n] + bhh[n];
    int gate = n >> 7, dd = n & 127;
    for (int r = 0; r < 16; r++)
        g_xwp[(((size_t)(t0 + r) * H_ + dd) << 4) + b * 4 + gate] = acc[r] + bb;
}

// ---------------- K2: sequential LSTM, gate-permuted, 1 barrier/step (R7 version) ----------------
__global__ void __launch_bounds__(512, 1) k_lstm4(const float* __restrict__ Whh) {
    __shared__ __half2 hbuf[2][4][72];
    int tid = threadIdx.x, wid = tid >> 5, lane = tid & 31;

    uint32_t afr[2][8][4];
#pragma unroll
    for (int m = 0; m < 2; m++)
#pragma unroll
        for (int ks = 0; ks < 8; ks++) {
            int rl = (m ? 256 : 0) + 8 * wid + (lane >> 2);
            int rh = rl + 128;
            int k0 = 16 * ks + (lane & 3) * 2;
            float2 wl0 = __ldg(reinterpret_cast<const float2*>(Whh + (size_t)rl * H_ + k0));
            float2 wh0 = __ldg(reinterpret_cast<const float2*>(Whh + (size_t)rh * H_ + k0));
            float2 wl8 = __ldg(reinterpret_cast<const float2*>(Whh + (size_t)rl * H_ + k0 + 8));
            float2 wh8 = __ldg(reinterpret_cast<const float2*>(Whh + (size_t)rh * H_ + k0 + 8));
            afr[m][ks][0] = pack_h2(wl0.x, wl0.y);
            afr[m][ks][1] = pack_h2(wh0.x, wh0.y);
            afr[m][ks][2] = pack_h2(wl8.x, wl8.y);
            afr[m][ks][3] = pack_h2(wh8.x, wh8.y);
        }

    if (tid < 288) {
        __half2 z = __half2half2(__float2half(0.f));
        (&hbuf[0][0][0])[tid] = z;
    }
    int bq = lane & 3;
    int hd = 8 * wid + (lane >> 2);
    int myb = ((bq & 1) << 1) | (bq >> 1);
    int sel = bq >> 1;
    int bb = (lane >> 2) & 3;
    int kq = lane & 3;
    float c = 0.f;
    __syncthreads();

    const float4* xwp4 = reinterpret_cast<const float4*>(g_xwp);
    float4 xa = __ldg(&xwp4[(size_t)hd * 4 + myb]);

    for (int t = 0; t < T_; t++) {
        int buf = t & 1;
        float acc0[4] = {0.f, 0.f, 0.f, 0.f};
        float acc1[4] = {0.f, 0.f, 0.f, 0.f};
#pragma unroll
        for (int ks = 0; ks < 8; ks++) {
            uint32_t b0 = *reinterpret_cast<const uint32_t*>(&hbuf[buf][bb][ks * 8 + kq]);
            uint32_t b1 = *reinterpret_cast<const uint32_t*>(&hbuf[buf][bb][ks * 8 + kq + 4]);
            asm volatile(
                "mma.sync.aligned.m16n8k16.row.col.f32.f16.f16.f32 "
                "{%0,%1,%2,%3}, {%4,%5,%6,%7}, {%8,%9}, {%0,%1,%2,%3};"
                : "+f"(acc0[0]), "+f"(acc0[1]), "+f"(acc0[2]), "+f"(acc0[3])
                : "r"(afr[0][ks][0]), "r"(afr[0][ks][1]),
                  "r"(afr[0][ks][2]), "r"(afr[0][ks][3]),
                  "r"(b0), "r"(b1));
            asm volatile(
                "mma.sync.aligned.m16n8k16.row.col.f32.f16.f16.f32 "
                "{%0,%1,%2,%3}, {%4,%5,%6,%7}, {%8,%9}, {%0,%1,%2,%3};"
                : "+f"(acc1[0]), "+f"(acc1[1]), "+f"(acc1[2]), "+f"(acc1[3])
                : "r"(afr[1][ks][0]), "r"(afr[1][ks][1]),
                  "r"(afr[1][ks][2]), "r"(afr[1][ks][3]),
                  "r"(b0), "r"(b1));
        }
        float4 xn = make_float4(0.f, 0.f, 0.f, 0.f);
        if (t + 1 < T_)
            xn = __ldg(&xwp4[((size_t)(t + 1) * H_ + hd) * 4 + myb]);

        float gi = (sel ? acc0[1] : acc0[0]) + xa.x;
        float gf = (sel ? acc0[3] : acc0[2]) + xa.y;
        float gg = (sel ? acc1[1] : acc1[0]) + xa.z;
        float go = (sel ? acc1[3] : acc1[2]) + xa.w;
        float si = sigmoid_fast(gi);
        float sf = sigmoid_fast(gf);
        float so = sigmoid_fast(go);
        c = sf * c + si * tanh_fast(gg);
        float h = so * tanh_fast(c);
        g_h[(size_t)(myb * T_ + t) * H_ + hd] = h;
        reinterpret_cast<__half*>(&hbuf[buf ^ 1][myb][0])[hd] = __float2half(h);
        __syncthreads();
        xa = xn;
    }
}

// ---------------- K3: veh = We@h, vdh = Wd@h, + pred_r + ||h||^2 ----------------
__global__ void k_vw(const float* __restrict__ We, const float* __restrict__ Wd,
                     const float* __restrict__ Wr, const float* __restrict__ br,
                     float* __restrict__ out_pr) {
    __shared__ __align__(16) float hsm[16][H_];
    __shared__ float wr_s[H_];
    int row0 = blockIdx.x * 16;
    int tid = threadIdx.x;
    for (int i = tid; i < 16 * H_; i += 256)
        hsm[i >> 7][i & 127] = g_h[(size_t)row0 * H_ + i];
    if (tid < H_) wr_s[tid] = Wr[tid];
    __syncthreads();
    int k = tid & 127;
    const float* M = (tid < 128) ? We : Wd;
    float* O = (tid < 128) ? g_weh : g_wdh;
    const float4* mrow = reinterpret_cast<const float4*>(M + (size_t)k * H_);
    float acc[16];
#pragma unroll
    for (int r = 0; r < 16; r++) acc[r] = 0.f;
#pragma unroll 4
    for (int k4 = 0; k4 < H_ / 4; k4++) {
        float4 w = __ldg(mrow + k4);
#pragma unroll
        for (int r = 0; r < 16; r++) {
            float4 h = *reinterpret_cast<const float4*>(&hsm[r][k4 * 4]);
            acc[r] += w.x * h.x + w.y * h.y + w.z * h.z + w.w * h.w;
        }
    }
    for (int r = 0; r < 16; r++)
        O[(size_t)(row0 + r) * H_ + k] = acc[r];

    int warp = tid >> 5, lane = tid & 31;
    float brv = __ldg(br);
#pragma unroll
    for (int rr = 0; rr < 2; rr++) {
        int r = warp * 2 + rr;
        float h0 = hsm[r][lane],      h1 = hsm[r][lane + 32];
        float h2 = hsm[r][lane + 64], h3 = hsm[r][lane + 96];
        float p = h0 * wr_s[lane]      + h1 * wr_s[lane + 32]
                + h2 * wr_s[lane + 64] + h3 * wr_s[lane + 96];
        float s = h0 * h0 + h1 * h1 + h2 * h2 + h3 * h3;
#pragma unroll
        for (int o = 16; o; o >>= 1) {
            p += __shfl_down_sync(0xffffffffu, p, o);
            s += __shfl_down_sync(0xffffffffu, s, o);
        }
        if (lane == 0) {
            out_pr[row0 + r] = 1.f / (1.f + __expf(-(p + brv)));
            g_hh[row0 + r] = s;
        }
    }
}

// ---------------- K4: sequential entity recurrence, 512 threads, 2 barriers/step ----------------
// pred_e partials split 8-ways (16 j-iters/thread). Dots/update on first 256 threads.
__global__ void __launch_bounds__(512, 1) k_ent3(const int* __restrict__ eids,
                                                 const int* __restrict__ sids,
                                                 const float* __restrict__ ents0,
                                                 const float* __restrict__ lamp,
                                                 float* __restrict__ out_pe) {
    __shared__ float entsT[H_][E_ + 1];
    __shared__ float dists[E_];
    __shared__ float veh_s[H_], h_s[H_], last_s[H_];
    __shared__ float red2[512];
    __shared__ float nred[4];    // ent . vdh partials
    __shared__ float nred2[4];   // ent . h partials
    int b = blockIdx.x, tid = threadIdx.x;
    float lam = *lamp;
    for (int i = tid; i < E_ * H_; i += 512) {
        int e = i >> 7, j = i & 127;
        entsT[j][e] = ents0[(size_t)(b * E_ + e) * H_ + j];
    }
    if (tid < E_) dists[tid] = 0.f;
    if (tid < H_) last_s[tid] = ents0[(size_t)b * E_ * H_ + tid];
    __syncthreads();
    int q = tid >> 6, e = tid & 63;       // 8 q-groups of 16 dims each
    int lane = tid & 31, warp = tid >> 5;
    int jd = tid & 127;

    // prefetch t=0
    float pv = 0.f, pd = 0.f, ph = 0.f;
    {
        size_t bt0 = (size_t)b * T_ * H_;
        if (tid < H_) {
            pv = __ldg(&g_weh[bt0 + tid]);
            pd = __ldg(&g_wdh[bt0 + tid]);
        }
        if (tid < 256) ph = __ldg(&g_h[bt0 + jd]);
    }
    int peid = __ldg(&eids[b * T_]);
    float psid = (float)__ldg(&sids[b * T_]);
    float phh = __ldg(&g_hh[b * T_]);

    for (int t = 0; t < T_; t++) {
        int bt = b * T_ + t;
        if (tid < H_) { veh_s[tid] = pv; h_s[tid] = ph; }
        int eid = peid;
        float sid = psid;
        float hh = phh;
        float vd = pd;     // own vdh (dim jd), register
        float hv = ph;     // own h (dim jd), register
        __syncthreads();  // S1: staging + prev-step updates visible
        // prefetch t+1
        if (t + 1 < T_) {
            size_t bt1 = (size_t)(bt + 1) * H_;
            if (tid < H_) {
                pv = __ldg(&g_weh[bt1 + tid]);
                pd = __ldg(&g_wdh[bt1 + tid]);
            }
            if (tid < 256) ph = __ldg(&g_h[bt1 + jd]);
            peid = __ldg(&eids[bt + 1]);
            psid = (float)__ldg(&sids[bt + 1]);
            phh = __ldg(&g_hh[bt + 1]);
        }
        // phase 1: exp term (pre-update dists)
        float expterm = 0.f;
        if (tid < E_) expterm = expf((dists[tid] - sid) * lam);
        // pred_e partials: thread (q,e) covers j in [16q, 16q+16)
        float p0 = 0.f, p1 = 0.f, p2 = 0.f, p3 = 0.f;
#pragma unroll
        for (int jj = 0; jj < 4; jj++) {
            int j = q * 16 + jj * 4;
            p0 += entsT[j][e]     * veh_s[j];
            p1 += entsT[j + 1][e] * veh_s[j + 1];
            p2 += entsT[j + 2][e] * veh_s[j + 2];
            p3 += entsT[j + 3][e] * veh_s[j + 3];
        }
        red2[tid] = (p0 + p1) + (p2 + p3);
        // dual dots from registers: warps 0-3 ent.vdh, warps 4-7 ent.h
        if (tid < 256) {
            float ent_val = entsT[jd][eid];
            float d = ent_val * ((tid < 128) ? vd : hv);
#pragma unroll
            for (int o = 16; o; o >>= 1) d += __shfl_down_sync(0xffffffffu, d, o);
            if (lane == 0) {
                if (warp < 4) nred[warp] = d;
                else          nred2[warp - 4] = d;
            }
        }
        __syncthreads();  // S2
        // phase 2
        if (tid < E_) {
            float pe = expterm;
#pragma unroll
            for (int qq = 0; qq < 8; qq++) pe += red2[tid + qq * 64];
            out_pe[(size_t)bt * E_ + tid] = pe;
        }
        float dotdv = nred[0] + nred[1] + nred[2] + nred[3];
        float doteh = nred2[0] + nred2[1] + nred2[2] + nred2[3];
        float delta = 1.f / (1.f + __expf(-dotdv));
        float omd = 1.f - delta;
        float n2 = delta * delta + 2.f * delta * omd * doteh + omd * omd * hh;
        float rn = rsqrtf(n2);
        if (tid < H_) {
            float u = delta * entsT[tid][eid] + omd * h_s[tid];
            float un = u * rn;
            float fs = (eid > 0) ? un : last_s[tid];
            g_fsrc[(size_t)bt * H_ + tid] = fs;
            entsT[tid][eid] = un;
            last_s[tid] = un;
        }
        if (tid == 0) { dists[eid] = sid; g_sel[bt] = (eid > 0) ? 1 : 0; }
        // next S1 orders these writes before next reads
    }
}

// ---------------- K5: ent_feat + z (fp16) ----------------
__global__ void k_feat(const float* __restrict__ WTe, const float* __restrict__ WTc) {
    __shared__ __align__(16) float fs[8][H_];
    int row0 = blockIdx.x * 8;
    int j = threadIdx.x;
    for (int i = j; i < 8 * H_; i += 128)
        fs[i >> 7][i & 127] = g_fsrc[(size_t)row0 * H_ + i];
    __syncthreads();
    float acc_e[8], acc_c[8];
#pragma unroll
    for (int r = 0; r < 8; r++) { acc_e[r] = 0.f; acc_c[r] = 0.f; }
    const float4* we4 = reinterpret_cast<const float4*>(WTe + (size_t)j * H_);
    const float4* wc4 = reinterpret_cast<const float4*>(WTc + (size_t)j * H_);
#pragma unroll 4
    for (int k4 = 0; k4 < H_ / 4; k4++) {
        float4 we = __ldg(we4 + k4);
        float4 wc = __ldg(wc4 + k4);
#pragma unroll
        for (int r = 0; r < 8; r++) {
            float4 f = *reinterpret_cast<const float4*>(&fs[r][k4 * 4]);
            acc_e[r] += we.x * f.x + we.y * f.y + we.z * f.z + we.w * f.w;
            acc_c[r] += wc.x * f.x + wc.y * f.y + wc.z * f.z + wc.w * f.w;
        }
    }
    for (int r = 0; r < 8; r++) {
        int bt = row0 + r;
        float feat = g_sel[bt] ? acc_e[r] : acc_c[r];
        float z = g_h[(size_t)bt * H_ + j] + feat;
        g_z16[(size_t)bt * H_ + j] = __float2half(z);
    }
}

// ---------------- K6: logits = z @ Wx^T + bx, 128x128 tiles ----------------
__global__ void __launch_bounds__(256, 2) k_logits(const float* __restrict__ bx,
                                                   float* __restrict__ out) {
    extern __shared__ __align__(16) __half smemh[];
    __half (*sA)[128] = reinterpret_cast<__half (*)[128]>(smemh);
    __half (*sB)[128] = reinterpret_cast<__half (*)[128]>(smemh + 128 * 128);
    int tid = threadIdx.x;
    int m0 = blockIdx.y * 128;
    int n0 = blockIdx.x * 128;
    {
        int r = tid >> 1;
        int cbase = (tid & 1) * 8;
        const uint4* src = reinterpret_cast<const uint4*>(g_z16) + (size_t)(m0 + r) * 16;
#pragma unroll
        for (int i = 0; i < 8; i++) {
            int c = cbase + i;
            uint4 v = src[c];
            *reinterpret_cast<uint4*>(&sA[r][(c ^ (r & 7)) << 3]) = v;
        }
    }
    {
        int r = tid >> 1;
        int cbase = (tid & 1) * 8;
        int v_ = n0 + r;
        const uint4* src = reinterpret_cast<const uint4*>(g_wx16) + (size_t)v_ * 16;
#pragma unroll
        for (int i = 0; i < 8; i++) {
            int c = cbase + i;
            uint4 v;
            if (v_ < V_) v = src[c];
            else { v.x = 0u; v.y = 0u; v.z = 0u; v.w = 0u; }
            *reinterpret_cast<uint4*>(&sB[r][(c ^ (r & 7)) << 3]) = v;
        }
    }
    __syncthreads();

    int lane = tid & 31, warp = tid >> 5;
    int wm = warp >> 1, wn = warp & 1;
    float acc[2][8][4];
#pragma unroll
    for (int mt = 0; mt < 2; mt++)
#pragma unroll
        for (int nt = 0; nt < 8; nt++)
#pragma unroll
            for (int i = 0; i < 4; i++) acc[mt][nt][i] = 0.f;

#pragma unroll
    for (int ks = 0; ks < 8; ks++) {
        uint32_t afrag[2][4];
#pragma unroll
        for (int mt = 0; mt < 2; mt++) {
            int row = wm * 32 + mt * 16 + (lane & 15);
            int chunk = ks * 2 + (lane >> 4);
            unsigned addr = (unsigned)__cvta_generic_to_shared(&sA[row][(chunk ^ (row & 7)) << 3]);
            asm volatile("ldmatrix.sync.aligned.m8n8.x4.shared.b16 {%0,%1,%2,%3}, [%4];"
                         : "=r"(afrag[mt][0]), "=r"(afrag[mt][1]),
                           "=r"(afrag[mt][2]), "=r"(afrag[mt][3]) : "r"(addr));
        }
        uint32_t bfrag[8][2];
#pragma unroll
        for (int nt = 0; nt < 8; nt++) {
            int row = wn * 64 + nt * 8 + (lane & 7);
            int chunk = ks * 2 + ((lane >> 3) & 1);
            unsigned addr = (unsigned)__cvta_generic_to_shared(&sB[row][(chunk ^ (row & 7)) << 3]);
            asm volatile("ldmatrix.sync.aligned.m8n8.x2.shared.b16 {%0,%1}, [%2];"
                         : "=r"(bfrag[nt][0]), "=r"(bfrag[nt][1]) : "r"(addr));
        }
#pragma unroll
        for (int mt = 0; mt < 2; mt++)
#pragma unroll
            for (int nt = 0; nt < 8; nt++) {
                asm volatile(
                    "mma.sync.aligned.m16n8k16.row.col.f32.f16.f16.f32 "
                    "{%0,%1,%2,%3}, {%4,%5,%6,%7}, {%8,%9}, {%0,%1,%2,%3};"
                    : "+f"(acc[mt][nt][0]), "+f"(acc[mt][nt][1]),
                      "+f"(acc[mt][nt][2]), "+f"(acc[mt][nt][3])
                    : "r"(afrag[mt][0]), "r"(afrag[mt][1]),
                      "r"(afrag[mt][2]), "r"(afrag[mt][3]),
                      "r"(bfrag[nt][0]), "r"(bfrag[nt][1]));
            }
    }
    int rrow = lane >> 2, col = (lane & 3) * 2;
#pragma unroll
    for (int mt = 0; mt < 2; mt++) {
#pragma unroll
        for (int nt = 0; nt < 8; nt++) {
            size_t gm = (size_t)(m0 + wm * 32 + mt * 16 + rrow);
            int gv = n0 + wn * 64 + nt * 8 + col;
            float* a = acc[mt][nt];
            if (gv < V_) {
                float b0 = bx[gv];
                out[gm * V_ + gv]       = a[0] + b0;
                out[(gm + 8) * V_ + gv] = a[2] + b0;
            }
            if (gv + 1 < V_) {
                float b1 = bx[gv + 1];
                out[gm * V_ + gv + 1]       = a[1] + b1;
                out[(gm + 8) * V_ + gv + 1] = a[3] + b1;
            }
        }
    }
}

// ---------------- launch ----------------
extern "C" void kernel_launch(void* const* d_in, const int* in_sizes, int n_in,
                              void* d_out, int out_size) {
    const int*   tokens = (const int*)d_in[0];
    const int*   eids   = (const int*)d_in[1];
    const int*   sids   = (const int*)d_in[2];
    const float* embed  = (const float*)d_in[3];
    const float* Wih    = (const float*)d_in[4];
    const float* Whh    = (const float*)d_in[5];
    const float* bih    = (const float*)d_in[6];
    const float* bhh    = (const float*)d_in[7];
    const float* Wr     = (const float*)d_in[8];
    const float* br     = (const float*)d_in[9];
    const float* We     = (const float*)d_in[10];
    const float* Wd     = (const float*)d_in[11];
    const float* WTe    = (const float*)d_in[12];
    const float* WTc    = (const float*)d_in[13];
    const float* Wx     = (const float*)d_in[14];
    const float* bx     = (const float*)d_in[15];
    const float* ents0  = (const float*)d_in[16];
    const float* lam    = (const float*)d_in[17];
    float* out = (float*)d_out;

    const size_t OFF_R = (size_t)B_ * T_ * V_;
    const size_t OFF_E = OFF_R + (size_t)B_ * T_;

    __half* wx16;
    cudaGetSymbolAddress((void**)&wx16, g_wx16);

    static int attr_set = 0;
    if (!attr_set) {
        cudaFuncSetAttribute(k_logits, cudaFuncAttributeMaxDynamicSharedMemorySize, 65536);
        attr_set = 1;
    }

    int nwx = V_ * H_;
    // order: k_ent3 at captured launch index 3; k_cvt after (logits at 6 still sees wx16)
    k_xw<<<dim3(T_ / 16, B_), 512>>>(tokens, embed, Wih, bih, bhh);   // 0
    k_lstm4<<<1, 512>>>(Whh);                                         // 1
    k_vw<<<(B_ * T_) / 16, 256>>>(We, Wd, Wr, br, out + OFF_R);       // 2
    k_ent3<<<B_, 512>>>(eids, sids, ents0, lam, out + OFF_E);         // 3  <- profiled
    k_cvt<<<(nwx + 255) / 256, 256>>>(Wx, wx16, nwx);                 // 4
    k_feat<<<(B_ * T_) / 8, 128>>>(WTe, WTc);                         // 5
    k_logits<<<dim3((V_ + 127) / 128, (B_ * T_) / 128), 256, 65536>>>(bx, out);  // 6
}

// round 10
// speedup vs baseline: 1.5255x; 1.1531x over previous
#include <cuda_runtime.h>
#include <cuda_fp16.h>
#include <cstdint>
#include <cstddef>

#define B_ 4
#define T_ 512
#define H_ 128
#define D_ 300
#define V_ 50257
#define E_ 64

// ---------------- static device scratch ----------------
__device__ float  g_xwp [T_*H_*16];         // gates pre-act, layout [t][dim][batch][gate]
__device__ float  g_h   [B_*T_*H_];         // LSTM hidden states
__device__ float  g_weh [B_*T_*H_];         // We @ h
__device__ float  g_wdh [B_*T_*H_];         // Wd @ h
__device__ float  g_hh  [B_*T_];            // ||h||^2
__device__ float  g_exp [B_*T_*E_];         // exp((dists - sid)*lam), precomputed
__device__ float  g_fsrc[B_*T_*H_];         // selected feature source vector
__device__ int    g_sel [B_*T_];            // eid > 0 flag
__device__ __half g_z16 [B_*T_*H_];         // z = h + ent_feat (fp16)
__device__ __half g_wx16[(size_t)V_*H_];    // Wx in fp16

__device__ __forceinline__ uint32_t pack_h2(float a, float b) {
    __half2 h = __floats2half2_rn(a, b);
    return *reinterpret_cast<uint32_t*>(&h);
}
__device__ __forceinline__ float tanh_fast(float x) {
    float y;
    asm("tanh.approx.f32 %0, %1;" : "=f"(y) : "f"(x));
    return y;
}
__device__ __forceinline__ float sigmoid_fast(float x) {
    return 0.5f * tanh_fast(0.5f * x) + 0.5f;
}

// ---------------- K0: Wx -> fp16 ----------------
__global__ void k_cvt(const float* __restrict__ src, __half* __restrict__ dst, int n) {
    int i = blockIdx.x * blockDim.x + threadIdx.x;
    if (i < n) dst[i] = __float2half(src[i]);
}

// ---------------- K1: xw (permuted) + dist/exp precompute + sel flags ----------------
__global__ void k_xw(const int* __restrict__ tokens, const float* __restrict__ embed,
                     const float* __restrict__ Wih, const float* __restrict__ bih,
                     const float* __restrict__ bhh, const int* __restrict__ eids,
                     const int* __restrict__ sids, const float* __restrict__ lamp) {
    int b = blockIdx.y;
    if (blockIdx.x == T_ / 16) {
        // dist walk block: thread e maintains last-sid for entity e, writes exp term
        int e = threadIdx.x;
        if (e < E_) {
            float lam = *lamp;
            float cur = 0.f;
            for (int t = 0; t < T_; t++) {
                int bt = b * T_ + t;
                int eid = __ldg(&eids[bt]);
                float sid = (float)__ldg(&sids[bt]);
                g_exp[(size_t)bt * E_ + e] = __expf((cur - sid) * lam);
                if (eid == e) cur = sid;
                if (e == 0) g_sel[bt] = (eid > 0) ? 1 : 0;
            }
        }
        return;
    }
    __shared__ __align__(16) float xs[16][D_];
    int t0 = blockIdx.x * 16, n = threadIdx.x;
    for (int i = n; i < 16 * D_; i += 512) {
        int r = i / D_, d = i - r * D_;
        xs[r][d] = embed[(size_t)tokens[b * T_ + t0 + r] * D_ + d];
    }
    __syncthreads();
    float acc[16];
#pragma unroll
    for (int r = 0; r < 16; r++) acc[r] = 0.f;
    const float4* wr = reinterpret_cast<const float4*>(Wih + (size_t)n * D_);
#pragma unroll 5
    for (int d4 = 0; d4 < D_ / 4; d4++) {
        float4 w = __ldg(wr + d4);
#pragma unroll
        for (int r = 0; r < 16; r++) {
            float4 x = *reinterpret_cast<const float4*>(&xs[r][d4 * 4]);
            acc[r] += w.x * x.x + w.y * x.y + w.z * x.z + w.w * x.w;
        }
    }
    float bb = bih[n] + bhh[n];
    int gate = n >> 7, dd = n & 127;
    for (int r = 0; r < 16; r++)
        g_xwp[(((size_t)(t0 + r) * H_ + dd) << 4) + b * 4 + gate] = acc[r] + bb;
}

// ---------------- K2: sequential LSTM, gate-permuted, 1 barrier/step ----------------
__global__ void __launch_bounds__(512, 1) k_lstm4(const float* __restrict__ Whh) {
    __shared__ __half2 hbuf[2][4][72];
    int tid = threadIdx.x, wid = tid >> 5, lane = tid & 31;

    uint32_t afr[2][8][4];
#pragma unroll
    for (int m = 0; m < 2; m++)
#pragma unroll
        for (int ks = 0; ks < 8; ks++) {
            int rl = (m ? 256 : 0) + 8 * wid + (lane >> 2);
            int rh = rl + 128;
            int k0 = 16 * ks + (lane & 3) * 2;
            float2 wl0 = __ldg(reinterpret_cast<const float2*>(Whh + (size_t)rl * H_ + k0));
            float2 wh0 = __ldg(reinterpret_cast<const float2*>(Whh + (size_t)rh * H_ + k0));
            float2 wl8 = __ldg(reinterpret_cast<const float2*>(Whh + (size_t)rl * H_ + k0 + 8));
            float2 wh8 = __ldg(reinterpret_cast<const float2*>(Whh + (size_t)rh * H_ + k0 + 8));
            afr[m][ks][0] = pack_h2(wl0.x, wl0.y);
            afr[m][ks][1] = pack_h2(wh0.x, wh0.y);
            afr[m][ks][2] = pack_h2(wl8.x, wl8.y);
            afr[m][ks][3] = pack_h2(wh8.x, wh8.y);
        }

    if (tid < 288) {
        __half2 z = __half2half2(__float2half(0.f));
        (&hbuf[0][0][0])[tid] = z;
    }
    int bq = lane & 3;
    int hd = 8 * wid + (lane >> 2);
    int myb = ((bq & 1) << 1) | (bq >> 1);
    int sel = bq >> 1;
    int bb = (lane >> 2) & 3;
    int kq = lane & 3;
    float c = 0.f;
    __syncthreads();

    const float4* xwp4 = reinterpret_cast<const float4*>(g_xwp);
    float4 xa = __ldg(&xwp4[(size_t)hd * 4 + myb]);

    for (int t = 0; t < T_; t++) {
        int buf = t & 1;
        float acc0[4] = {0.f, 0.f, 0.f, 0.f};
        float acc1[4] = {0.f, 0.f, 0.f, 0.f};
#pragma unroll
        for (int ks = 0; ks < 8; ks++) {
            uint32_t b0 = *reinterpret_cast<const uint32_t*>(&hbuf[buf][bb][ks * 8 + kq]);
            uint32_t b1 = *reinterpret_cast<const uint32_t*>(&hbuf[buf][bb][ks * 8 + kq + 4]);
            asm volatile(
                "mma.sync.aligned.m16n8k16.row.col.f32.f16.f16.f32 "
                "{%0,%1,%2,%3}, {%4,%5,%6,%7}, {%8,%9}, {%0,%1,%2,%3};"
                : "+f"(acc0[0]), "+f"(acc0[1]), "+f"(acc0[2]), "+f"(acc0[3])
                : "r"(afr[0][ks][0]), "r"(afr[0][ks][1]),
                  "r"(afr[0][ks][2]), "r"(afr[0][ks][3]),
                  "r"(b0), "r"(b1));
            asm volatile(
                "mma.sync.aligned.m16n8k16.row.col.f32.f16.f16.f32 "
                "{%0,%1,%2,%3}, {%4,%5,%6,%7}, {%8,%9}, {%0,%1,%2,%3};"
                : "+f"(acc1[0]), "+f"(acc1[1]), "+f"(acc1[2]), "+f"(acc1[3])
                : "r"(afr[1][ks][0]), "r"(afr[1][ks][1]),
                  "r"(afr[1][ks][2]), "r"(afr[1][ks][3]),
                  "r"(b0), "r"(b1));
        }
        float4 xn = make_float4(0.f, 0.f, 0.f, 0.f);
        if (t + 1 < T_)
            xn = __ldg(&xwp4[((size_t)(t + 1) * H_ + hd) * 4 + myb]);

        float gi = (sel ? acc0[1] : acc0[0]) + xa.x;
        float gf = (sel ? acc0[3] : acc0[2]) + xa.y;
        float gg = (sel ? acc1[1] : acc1[0]) + xa.z;
        float go = (sel ? acc1[3] : acc1[2]) + xa.w;
        float si = sigmoid_fast(gi);
        float sf = sigmoid_fast(gf);
        float so = sigmoid_fast(go);
        c = sf * c + si * tanh_fast(gg);
        float h = so * tanh_fast(c);
        g_h[(size_t)(myb * T_ + t) * H_ + hd] = h;
        reinterpret_cast<__half*>(&hbuf[buf ^ 1][myb][0])[hd] = __float2half(h);
        __syncthreads();
        xa = xn;
    }
}

// ---------------- K3: veh = We@h, vdh = Wd@h, + pred_r + ||h||^2 ----------------
__global__ void k_vw(const float* __restrict__ We, const float* __restrict__ Wd,
                     const float* __restrict__ Wr, const float* __restrict__ br,
                     float* __restrict__ out_pr) {
    __shared__ __align__(16) float hsm[16][H_];
    __shared__ float wr_s[H_];
    int row0 = blockIdx.x * 16;
    int tid = threadIdx.x;
    for (int i = tid; i < 16 * H_; i += 256)
        hsm[i >> 7][i & 127] = g_h[(size_t)row0 * H_ + i];
    if (tid < H_) wr_s[tid] = Wr[tid];
    __syncthreads();
    int k = tid & 127;
    const float* M = (tid < 128) ? We : Wd;
    float* O = (tid < 128) ? g_weh : g_wdh;
    const float4* mrow = reinterpret_cast<const float4*>(M + (size_t)k * H_);
    float acc[16];
#pragma unroll
    for (int r = 0; r < 16; r++) acc[r] = 0.f;
#pragma unroll 4
    for (int k4 = 0; k4 < H_ / 4; k4++) {
        float4 w = __ldg(mrow + k4);
#pragma unroll
        for (int r = 0; r < 16; r++) {
            float4 h = *reinterpret_cast<const float4*>(&hsm[r][k4 * 4]);
            acc[r] += w.x * h.x + w.y * h.y + w.z * h.z + w.w * h.w;
        }
    }
    for (int r = 0; r < 16; r++)
        O[(size_t)(row0 + r) * H_ + k] = acc[r];

    int warp = tid >> 5, lane = tid & 31;
    float brv = __ldg(br);
#pragma unroll
    for (int rr = 0; rr < 2; rr++) {
        int r = warp * 2 + rr;
        float h0 = hsm[r][lane],      h1 = hsm[r][lane + 32];
        float h2 = hsm[r][lane + 64], h3 = hsm[r][lane + 96];
        float p = h0 * wr_s[lane]      + h1 * wr_s[lane + 32]
                + h2 * wr_s[lane + 64] + h3 * wr_s[lane + 96];
        float s = h0 * h0 + h1 * h1 + h2 * h2 + h3 * h3;
#pragma unroll
        for (int o = 16; o; o >>= 1) {
            p += __shfl_down_sync(0xffffffffu, p, o);
            s += __shfl_down_sync(0xffffffffu, s, o);
        }
        if (lane == 0) {
            out_pr[row0 + r] = 1.f / (1.f + __expf(-(p + brv)));
            g_hh[row0 + r] = s;
        }
    }
}

// ---------------- K4: sequential entity recurrence, pure-barrier steps ----------------
// warps 0-3: redundant dual-dot butterfly -> delta,rn local; own 1 dim each.
// warps 4-11: pred_e e-major (4 lanes/e, 32 j/lane, bank-phased), direct STG.
// warps 12-15: staging/prefetch of veh/vdh/h.
__global__ void __launch_bounds__(512, 1) k_ent4(const int* __restrict__ eids,
                                                 const float* __restrict__ ents0,
                                                 float* __restrict__ out_pe) {
    __shared__ float entsT[H_][E_ + 1];
    __shared__ float veh_s[H_], vdh_s[H_], h_s[H_];
    int b = blockIdx.x, tid = threadIdx.x;
    int warp = tid >> 5, lane = tid & 31;

    for (int i = tid; i < E_ * H_; i += 512) {
        int e = i >> 7, j = i & 127;
        entsT[j][e] = ents0[(size_t)(b * E_ + e) * H_ + j];
    }
    int d0 = warp * 32 + lane;                 // updater-owned dim (warp<4)
    float last_r = 0.f;
    if (warp < 4) last_r = __ldg(&ents0[(size_t)b * E_ * H_ + d0]);

    int ww = warp - 4;
    int e_pe = ww * 8 + (lane >> 2);           // pred_e entity (warps 4-11)
    int lg = lane & 3;

    int sdim = tid - 384;                      // staging dim (warps 12-15)
    float pv = 0.f, pd = 0.f, ph = 0.f;
    if (tid >= 384) {
        size_t bt0 = (size_t)b * T_ * H_;
        pv = __ldg(&g_weh[bt0 + sdim]);
        pd = __ldg(&g_wdh[bt0 + sdim]);
        ph = __ldg(&g_h[bt0 + sdim]);
    }
    int peid = __ldg(&eids[b * T_]);
    float phh = 0.f;
    if (warp < 4) phh = __ldg(&g_hh[b * T_]);
    float pexp = 0.f;
    if (warp >= 4 && warp < 12) pexp = __ldg(&g_exp[(size_t)(b * T_) * E_ + e_pe]);
    __syncthreads();

    for (int t = 0; t < T_; t++) {
        int bt = b * T_ + t;
        if (tid >= 384) { veh_s[sdim] = pv; vdh_s[sdim] = pd; h_s[sdim] = ph; }
        int eid = peid;
        float hh = phh;
        float expt = pexp;
        __syncthreads();   // S1: staging + prev entsT updates visible
        if (t + 1 < T_) {
            if (tid >= 384) {
                size_t bt1 = (size_t)(bt + 1) * H_;
                pv = __ldg(&g_weh[bt1 + sdim]);
                pd = __ldg(&g_wdh[bt1 + sdim]);
                ph = __ldg(&g_h[bt1 + sdim]);
            }
            peid = __ldg(&eids[bt + 1]);
            if (warp < 4) phh = __ldg(&g_hh[bt + 1]);
            if (warp >= 4 && warp < 12) pexp = __ldg(&g_exp[(size_t)(bt + 1) * E_ + e_pe]);
        }
        float un = 0.f;
        if (warp < 4) {
            // dual dot over all 128 dims, redundant per warp
            float ev0 = entsT[lane][eid];
            float ev1 = entsT[lane + 32][eid];
            float ev2 = entsT[lane + 64][eid];
            float ev3 = entsT[lane + 96][eid];
            float w0 = vdh_s[lane],      w1 = vdh_s[lane + 32];
            float w2 = vdh_s[lane + 64], w3 = vdh_s[lane + 96];
            float hv0 = h_s[lane],       hv1 = h_s[lane + 32];
            float hv2 = h_s[lane + 64],  hv3 = h_s[lane + 96];
            float dv = ev0 * w0 + ev1 * w1 + ev2 * w2 + ev3 * w3;
            float dh = ev0 * hv0 + ev1 * hv1 + ev2 * hv2 + ev3 * hv3;
#pragma unroll
            for (int o = 16; o; o >>= 1) {
                dv += __shfl_xor_sync(0xffffffffu, dv, o);
                dh += __shfl_xor_sync(0xffffffffu, dh, o);
            }
            float delta = 1.f / (1.f + __expf(-dv));
            float omd = 1.f - delta;
            float n2 = delta * delta + 2.f * delta * omd * dh + omd * omd * hh;
            float rn = rsqrtf(n2);
            float ev_own = (warp == 0) ? ev0 : (warp == 1) ? ev1 : (warp == 2) ? ev2 : ev3;
            float hv_own = (warp == 0) ? hv0 : (warp == 1) ? hv1 : (warp == 2) ? hv2 : hv3;
            un = (delta * ev_own + omd * hv_own) * rn;
        } else if (warp < 12) {
            // pred_e: e fixed per 4-lane group, 32 j per lane, bank-phased
            float s = 0.f;
#pragma unroll
            for (int i = 0; i < 32; i++) {
                int j = lg * 32 + ((i + 8 * lg) & 31);
                s += entsT[j][e_pe] * veh_s[j];
            }
            s += __shfl_xor_sync(0xffffffffu, s, 1);
            s += __shfl_xor_sync(0xffffffffu, s, 2);
            if (lg == 0) out_pe[(size_t)bt * E_ + e_pe] = s + expt;
        }
        __syncthreads();   // S2: all entsT reads done before update
        if (warp < 4) {
            entsT[d0][eid] = un;
            g_fsrc[(size_t)bt * H_ + d0] = (eid > 0) ? un : last_r;
            last_r = un;
        }
    }
}

// ---------------- K5: ent_feat + z (fp16) ----------------
__global__ void k_feat(const float* __restrict__ WTe, const float* __restrict__ WTc) {
    __shared__ __align__(16) float fs[8][H_];
    int row0 = blockIdx.x * 8;
    int j = threadIdx.x;
    for (int i = j; i < 8 * H_; i += 128)
        fs[i >> 7][i & 127] = g_fsrc[(size_t)row0 * H_ + i];
    __syncthreads();
    float acc_e[8], acc_c[8];
#pragma unroll
    for (int r = 0; r < 8; r++) { acc_e[r] = 0.f; acc_c[r] = 0.f; }
    const float4* we4 = reinterpret_cast<const float4*>(WTe + (size_t)j * H_);
    const float4* wc4 = reinterpret_cast<const float4*>(WTc + (size_t)j * H_);
#pragma unroll 4
    for (int k4 = 0; k4 < H_ / 4; k4++) {
        float4 we = __ldg(we4 + k4);
        float4 wc = __ldg(wc4 + k4);
#pragma unroll
        for (int r = 0; r < 8; r++) {
            float4 f = *reinterpret_cast<const float4*>(&fs[r][k4 * 4]);
            acc_e[r] += we.x * f.x + we.y * f.y + we.z * f.z + we.w * f.w;
            acc_c[r] += wc.x * f.x + wc.y * f.y + wc.z * f.z + wc.w * f.w;
        }
    }
    for (int r = 0; r < 8; r++) {
        int bt = row0 + r;
        float feat = g_sel[bt] ? acc_e[r] : acc_c[r];
        float z = g_h[(size_t)bt * H_ + j] + feat;
        g_z16[(size_t)bt * H_ + j] = __float2half(z);
    }
}

// ---------------- K6: logits = z @ Wx^T + bx, 128x128 tiles ----------------
__global__ void __launch_bounds__(256, 2) k_logits(const float* __restrict__ bx,
                                                   float* __restrict__ out) {
    extern __shared__ __align__(16) __half smemh[];
    __half (*sA)[128] = reinterpret_cast<__half (*)[128]>(smemh);
    __half (*sB)[128] = reinterpret_cast<__half (*)[128]>(smemh + 128 * 128);
    int tid = threadIdx.x;
    int m0 = blockIdx.y * 128;
    int n0 = blockIdx.x * 128;
    {
        int r = tid >> 1;
        int cbase = (tid & 1) * 8;
        const uint4* src = reinterpret_cast<const uint4*>(g_z16) + (size_t)(m0 + r) * 16;
#pragma unroll
        for (int i = 0; i < 8; i++) {
            int c = cbase + i;
            uint4 v = src[c];
            *reinterpret_cast<uint4*>(&sA[r][(c ^ (r & 7)) << 3]) = v;
        }
    }
    {
        int r = tid >> 1;
        int cbase = (tid & 1) * 8;
        int v_ = n0 + r;
        const uint4* src = reinterpret_cast<const uint4*>(g_wx16) + (size_t)v_ * 16;
#pragma unroll
        for (int i = 0; i < 8; i++) {
            int c = cbase + i;
            uint4 v;
            if (v_ < V_) v = src[c];
            else { v.x = 0u; v.y = 0u; v.z = 0u; v.w = 0u; }
            *reinterpret_cast<uint4*>(&sB[r][(c ^ (r & 7)) << 3]) = v;
        }
    }
    __syncthreads();

    int lane = tid & 31, warp = tid >> 5;
    int wm = warp >> 1, wn = warp & 1;
    float acc[2][8][4];
#pragma unroll
    for (int mt = 0; mt < 2; mt++)
#pragma unroll
        for (int nt = 0; nt < 8; nt++)
#pragma unroll
            for (int i = 0; i < 4; i++) acc[mt][nt][i] = 0.f;

#pragma unroll
    for (int ks = 0; ks < 8; ks++) {
        uint32_t afrag[2][4];
#pragma unroll
        for (int mt = 0; mt < 2; mt++) {
            int row = wm * 32 + mt * 16 + (lane & 15);
            int chunk = ks * 2 + (lane >> 4);
            unsigned addr = (unsigned)__cvta_generic_to_shared(&sA[row][(chunk ^ (row & 7)) << 3]);
            asm volatile("ldmatrix.sync.aligned.m8n8.x4.shared.b16 {%0,%1,%2,%3}, [%4];"
                         : "=r"(afrag[mt][0]), "=r"(afrag[mt][1]),
                           "=r"(afrag[mt][2]), "=r"(afrag[mt][3]) : "r"(addr));
        }
        uint32_t bfrag[8][2];
#pragma unroll
        for (int nt = 0; nt < 8; nt++) {
            int row = wn * 64 + nt * 8 + (lane & 7);
            int chunk = ks * 2 + ((lane >> 3) & 1);
            unsigned addr = (unsigned)__cvta_generic_to_shared(&sB[row][(chunk ^ (row & 7)) << 3]);
            asm volatile("ldmatrix.sync.aligned.m8n8.x2.shared.b16 {%0,%1}, [%2];"
                         : "=r"(bfrag[nt][0]), "=r"(bfrag[nt][1]) : "r"(addr));
        }
#pragma unroll
        for (int mt = 0; mt < 2; mt++)
#pragma unroll
            for (int nt = 0; nt < 8; nt++) {
                asm volatile(
                    "mma.sync.aligned.m16n8k16.row.col.f32.f16.f16.f32 "
                    "{%0,%1,%2,%3}, {%4,%5,%6,%7}, {%8,%9}, {%0,%1,%2,%3};"
                    : "+f"(acc[mt][nt][0]), "+f"(acc[mt][nt][1]),
                      "+f"(acc[mt][nt][2]), "+f"(acc[mt][nt][3])
                    : "r"(afrag[mt][0]), "r"(afrag[mt][1]),
                      "r"(afrag[mt][2]), "r"(afrag[mt][3]),
                      "r"(bfrag[nt][0]), "r"(bfrag[nt][1]));
            }
    }
    int rrow = lane >> 2, col = (lane & 3) * 2;
#pragma unroll
    for (int mt = 0; mt < 2; mt++) {
#pragma unroll
        for (int nt = 0; nt < 8; nt++) {
            size_t gm = (size_t)(m0 + wm * 32 + mt * 16 + rrow);
            int gv = n0 + wn * 64 + nt * 8 + col;
            float* a = acc[mt][nt];
            if (gv < V_) {
                float b0 = bx[gv];
                out[gm * V_ + gv]       = a[0] + b0;
                out[(gm + 8) * V_ + gv] = a[2] + b0;
            }
            if (gv + 1 < V_) {
                float b1 = bx[gv + 1];
                out[gm * V_ + gv + 1]       = a[1] + b1;
                out[(gm + 8) * V_ + gv + 1] = a[3] + b1;
            }
        }
    }
}

// ---------------- launch ----------------
extern "C" void kernel_launch(void* const* d_in, const int* in_sizes, int n_in,
                              void* d_out, int out_size) {
    const int*   tokens = (const int*)d_in[0];
    const int*   eids   = (const int*)d_in[1];
    const int*   sids   = (const int*)d_in[2];
    const float* embed  = (const float*)d_in[3];
    const float* Wih    = (const float*)d_in[4];
    const float* Whh    = (const float*)d_in[5];
    const float* bih    = (const float*)d_in[6];
    const float* bhh    = (const float*)d_in[7];
    const float* Wr     = (const float*)d_in[8];
    const float* br     = (const float*)d_in[9];
    const float* We     = (const float*)d_in[10];
    const float* Wd     = (const float*)d_in[11];
    const float* WTe    = (const float*)d_in[12];
    const float* WTc    = (const float*)d_in[13];
    const float* Wx     = (const float*)d_in[14];
    const float* bx     = (const float*)d_in[15];
    const float* ents0  = (const float*)d_in[16];
    const float* lam    = (const float*)d_in[17];
    float* out = (float*)d_out;

    const size_t OFF_R = (size_t)B_ * T_ * V_;
    const size_t OFF_E = OFF_R + (size_t)B_ * T_;

    __half* wx16;
    cudaGetSymbolAddress((void**)&wx16, g_wx16);

    static int attr_set = 0;
    if (!attr_set) {
        cudaFuncSetAttribute(k_logits, cudaFuncAttributeMaxDynamicSharedMemorySize, 65536);
        attr_set = 1;
    }

    int nwx = V_ * H_;
    // k_ent4 kept at captured launch index 3 for profiling
    k_xw<<<dim3(T_ / 16 + 1, B_), 512>>>(tokens, embed, Wih, bih, bhh,
                                         eids, sids, lam);                  // 0
    k_lstm4<<<1, 512>>>(Whh);                                               // 1
    k_vw<<<(B_ * T_) / 16, 256>>>(We, Wd, Wr, br, out + OFF_R);             // 2
    k_ent4<<<B_, 512>>>(eids, ents0, out + OFF_E);                          // 3  <- profiled
    k_cvt<<<(nwx + 255) / 256, 256>>>(Wx, wx16, nwx);                       // 4
    k_feat<<<(B_ * T_) / 8, 128>>>(WTe, WTc);                               // 5
    k_logits<<<dim3((V_ + 127) / 128, (B_ * T_) / 128), 256, 65536>>>(bx, out);  // 6
}

// round 11
// speedup vs baseline: 1.6489x; 1.0809x over previous
#include <cuda_runtime.h>
#include <cuda_fp16.h>
#include <cstdint>
#include <cstddef>

#define B_ 4
#define T_ 512
#define H_ 128
#define D_ 300
#define V_ 50257
#define E_ 64

// ---------------- static device scratch ----------------
__device__ float  g_xwp [T_*H_*16];         // gates pre-act, layout [t][dim][batch][gate]
__device__ float  g_h   [B_*T_*H_];         // LSTM hidden states
__device__ float  g_weh [B_*T_*H_];         // We @ h
__device__ float  g_wdh [B_*T_*H_];         // Wd @ h
__device__ float  g_hh  [B_*T_];            // ||h||^2
__device__ float  g_exp [B_*T_*E_];         // exp((dists - sid)*lam), precomputed
__device__ int    g_lut [B_*T_*E_];         // last update step of entity e before t (-1: none)
__device__ float  g_un  [B_*T_*H_];         // un vector written at every step
__device__ float  g_fsrc[B_*T_*H_];         // selected feature source vector
__device__ int    g_sel [B_*T_];            // eid > 0 flag
__device__ __half g_z16 [B_*T_*H_];         // z = h + ent_feat (fp16)
__device__ __half g_wx16[(size_t)V_*H_];    // Wx in fp16

__device__ __forceinline__ uint32_t pack_h2(float a, float b) {
    __half2 h = __floats2half2_rn(a, b);
    return *reinterpret_cast<uint32_t*>(&h);
}
__device__ __forceinline__ float tanh_fast(float x) {
    float y;
    asm("tanh.approx.f32 %0, %1;" : "=f"(y) : "f"(x));
    return y;
}
__device__ __forceinline__ float sigmoid_fast(float x) {
    return 0.5f * tanh_fast(0.5f * x) + 0.5f;
}

// ---------------- K0: Wx -> fp16 ----------------
__global__ void k_cvt(const float* __restrict__ src, __half* __restrict__ dst, int n) {
    int i = blockIdx.x * blockDim.x + threadIdx.x;
    if (i < n) dst[i] = __float2half(src[i]);
}

// ---------------- K1: xw (permuted) + dist/exp/lut walk + sel flags ----------------
__global__ void k_xw(const int* __restrict__ tokens, const float* __restrict__ embed,
                     const float* __restrict__ Wih, const float* __restrict__ bih,
                     const float* __restrict__ bhh, const int* __restrict__ eids,
                     const int* __restrict__ sids, const float* __restrict__ lamp) {
    int b = blockIdx.y;
    if (blockIdx.x == T_ / 16) {
        // walk block: thread e maintains last sid + last update index for entity e
        int e = threadIdx.x;
        if (e < E_) {
            float lam = *lamp;
            float cur = 0.f;
            int idx = -1;
            for (int t = 0; t < T_; t++) {
                int bt = b * T_ + t;
                int eid = __ldg(&eids[bt]);
                float sid = (float)__ldg(&sids[bt]);
                g_exp[(size_t)bt * E_ + e] = __expf((cur - sid) * lam);
                g_lut[(size_t)bt * E_ + e] = idx;
                if (eid == e) { cur = sid; idx = t; }
                if (e == 0) g_sel[bt] = (eid > 0) ? 1 : 0;
            }
        }
        return;
    }
    __shared__ __align__(16) float xs[16][D_];
    int t0 = blockIdx.x * 16, n = threadIdx.x;
    for (int i = n; i < 16 * D_; i += 512) {
        int r = i / D_, d = i - r * D_;
        xs[r][d] = embed[(size_t)tokens[b * T_ + t0 + r] * D_ + d];
    }
    __syncthreads();
    float acc[16];
#pragma unroll
    for (int r = 0; r < 16; r++) acc[r] = 0.f;
    const float4* wr = reinterpret_cast<const float4*>(Wih + (size_t)n * D_);
#pragma unroll 5
    for (int d4 = 0; d4 < D_ / 4; d4++) {
        float4 w = __ldg(wr + d4);
#pragma unroll
        for (int r = 0; r < 16; r++) {
            float4 x = *reinterpret_cast<const float4*>(&xs[r][d4 * 4]);
            acc[r] += w.x * x.x + w.y * x.y + w.z * x.z + w.w * x.w;
        }
    }
    float bb = bih[n] + bhh[n];
    int gate = n >> 7, dd = n & 127;
    for (int r = 0; r < 16; r++)
        g_xwp[(((size_t)(t0 + r) * H_ + dd) << 4) + b * 4 + gate] = acc[r] + bb;
}

// ---------------- K2: sequential LSTM, gate-permuted, 1 barrier/step ----------------
__global__ void __launch_bounds__(512, 1) k_lstm4(const float* __restrict__ Whh) {
    __shared__ __half2 hbuf[2][4][72];
    int tid = threadIdx.x, wid = tid >> 5, lane = tid & 31;

    uint32_t afr[2][8][4];
#pragma unroll
    for (int m = 0; m < 2; m++)
#pragma unroll
        for (int ks = 0; ks < 8; ks++) {
            int rl = (m ? 256 : 0) + 8 * wid + (lane >> 2);
            int rh = rl + 128;
            int k0 = 16 * ks + (lane & 3) * 2;
            float2 wl0 = __ldg(reinterpret_cast<const float2*>(Whh + (size_t)rl * H_ + k0));
            float2 wh0 = __ldg(reinterpret_cast<const float2*>(Whh + (size_t)rh * H_ + k0));
            float2 wl8 = __ldg(reinterpret_cast<const float2*>(Whh + (size_t)rl * H_ + k0 + 8));
            float2 wh8 = __ldg(reinterpret_cast<const float2*>(Whh + (size_t)rh * H_ + k0 + 8));
            afr[m][ks][0] = pack_h2(wl0.x, wl0.y);
            afr[m][ks][1] = pack_h2(wh0.x, wh0.y);
            afr[m][ks][2] = pack_h2(wl8.x, wl8.y);
            afr[m][ks][3] = pack_h2(wh8.x, wh8.y);
        }

    if (tid < 288) {
        __half2 z = __half2half2(__float2half(0.f));
        (&hbuf[0][0][0])[tid] = z;
    }
    int bq = lane & 3;
    int hd = 8 * wid + (lane >> 2);
    int myb = ((bq & 1) << 1) | (bq >> 1);
    int sel = bq >> 1;
    int bb = (lane >> 2) & 3;
    int kq = lane & 3;
    float c = 0.f;
    __syncthreads();

    const float4* xwp4 = reinterpret_cast<const float4*>(g_xwp);
    float4 xa = __ldg(&xwp4[(size_t)hd * 4 + myb]);

    for (int t = 0; t < T_; t++) {
        int buf = t & 1;
        float acc0[4] = {0.f, 0.f, 0.f, 0.f};
        float acc1[4] = {0.f, 0.f, 0.f, 0.f};
#pragma unroll
        for (int ks = 0; ks < 8; ks++) {
            uint32_t b0 = *reinterpret_cast<const uint32_t*>(&hbuf[buf][bb][ks * 8 + kq]);
            uint32_t b1 = *reinterpret_cast<const uint32_t*>(&hbuf[buf][bb][ks * 8 + kq + 4]);
            asm volatile(
                "mma.sync.aligned.m16n8k16.row.col.f32.f16.f16.f32 "
                "{%0,%1,%2,%3}, {%4,%5,%6,%7}, {%8,%9}, {%0,%1,%2,%3};"
                : "+f"(acc0[0]), "+f"(acc0[1]), "+f"(acc0[2]), "+f"(acc0[3])
                : "r"(afr[0][ks][0]), "r"(afr[0][ks][1]),
                  "r"(afr[0][ks][2]), "r"(afr[0][ks][3]),
                  "r"(b0), "r"(b1));
            asm volatile(
                "mma.sync.aligned.m16n8k16.row.col.f32.f16.f16.f32 "
                "{%0,%1,%2,%3}, {%4,%5,%6,%7}, {%8,%9}, {%0,%1,%2,%3};"
                : "+f"(acc1[0]), "+f"(acc1[1]), "+f"(acc1[2]), "+f"(acc1[3])
                : "r"(afr[1][ks][0]), "r"(afr[1][ks][1]),
                  "r"(afr[1][ks][2]), "r"(afr[1][ks][3]),
                  "r"(b0), "r"(b1));
        }
        float4 xn = make_float4(0.f, 0.f, 0.f, 0.f);
        if (t + 1 < T_)
            xn = __ldg(&xwp4[((size_t)(t + 1) * H_ + hd) * 4 + myb]);

        float gi = (sel ? acc0[1] : acc0[0]) + xa.x;
        float gf = (sel ? acc0[3] : acc0[2]) + xa.y;
        float gg = (sel ? acc1[1] : acc1[0]) + xa.z;
        float go = (sel ? acc1[3] : acc1[2]) + xa.w;
        float si = sigmoid_fast(gi);
        float sf = sigmoid_fast(gf);
        float so = sigmoid_fast(go);
        c = sf * c + si * tanh_fast(gg);
        float h = so * tanh_fast(c);
        g_h[(size_t)(myb * T_ + t) * H_ + hd] = h;
        reinterpret_cast<__half*>(&hbuf[buf ^ 1][myb][0])[hd] = __float2half(h);
        __syncthreads();
        xa = xn;
    }
}

// ---------------- K3: veh = We@h, vdh = Wd@h, + pred_r + ||h||^2 ----------------
__global__ void k_vw(const float* __restrict__ We, const float* __restrict__ Wd,
                     const float* __restrict__ Wr, const float* __restrict__ br,
                     float* __restrict__ out_pr) {
    __shared__ __align__(16) float hsm[16][H_];
    __shared__ float wr_s[H_];
    int row0 = blockIdx.x * 16;
    int tid = threadIdx.x;
    for (int i = tid; i < 16 * H_; i += 256)
        hsm[i >> 7][i & 127] = g_h[(size_t)row0 * H_ + i];
    if (tid < H_) wr_s[tid] = Wr[tid];
    __syncthreads();
    int k = tid & 127;
    const float* M = (tid < 128) ? We : Wd;
    float* O = (tid < 128) ? g_weh : g_wdh;
    const float4* mrow = reinterpret_cast<const float4*>(M + (size_t)k * H_);
    float acc[16];
#pragma unroll
    for (int r = 0; r < 16; r++) acc[r] = 0.f;
#pragma unroll 4
    for (int k4 = 0; k4 < H_ / 4; k4++) {
        float4 w = __ldg(mrow + k4);
#pragma unroll
        for (int r = 0; r < 16; r++) {
            float4 h = *reinterpret_cast<const float4*>(&hsm[r][k4 * 4]);
            acc[r] += w.x * h.x + w.y * h.y + w.z * h.z + w.w * h.w;
        }
    }
    for (int r = 0; r < 16; r++)
        O[(size_t)(row0 + r) * H_ + k] = acc[r];

    int warp = tid >> 5, lane = tid & 31;
    float brv = __ldg(br);
#pragma unroll
    for (int rr = 0; rr < 2; rr++) {
        int r = warp * 2 + rr;
        float h0 = hsm[r][lane],      h1 = hsm[r][lane + 32];
        float h2 = hsm[r][lane + 64], h3 = hsm[r][lane + 96];
        float p = h0 * wr_s[lane]      + h1 * wr_s[lane + 32]
                + h2 * wr_s[lane + 64] + h3 * wr_s[lane + 96];
        float s = h0 * h0 + h1 * h1 + h2 * h2 + h3 * h3;
#pragma unroll
        for (int o = 16; o; o >>= 1) {
            p += __shfl_down_sync(0xffffffffu, p, o);
            s += __shfl_down_sync(0xffffffffu, s, o);
        }
        if (lane == 0) {
            out_pr[row0 + r] = 1.f / (1.f + __expf(-(p + brv)));
            g_hh[row0 + r] = s;
        }
    }
}

// ---------------- K4: sequential entity recurrence (update only), 256 threads ----------------
// warps 0-3: redundant dual-dot butterfly -> delta, rn; own 1 dim each; write un
// to entsT col + g_un row + g_fsrc. warps 4-7: staging/prefetch of vdh/h.
__global__ void __launch_bounds__(256, 1) k_ent5(const int* __restrict__ eids,
                                                 const float* __restrict__ ents0) {
    __shared__ float entsT[H_][E_ + 1];
    __shared__ float vdh_s[H_], h_s[H_];
    int b = blockIdx.x, tid = threadIdx.x;
    int warp = tid >> 5, lane = tid & 31;

    for (int i = tid; i < E_ * H_; i += 256) {
        int e = i >> 7, j = i & 127;
        entsT[j][e] = ents0[(size_t)(b * E_ + e) * H_ + j];
    }
    int d0 = warp * 32 + lane;                 // updater-owned dim (warp<4)
    float last_r = 0.f;
    if (warp < 4) last_r = __ldg(&ents0[(size_t)b * E_ * H_ + d0]);

    int sdim = tid - 128;                      // staging dim (warps 4-7)
    float pd = 0.f, ph = 0.f;
    if (tid >= 128) {
        size_t bt0 = (size_t)b * T_ * H_;
        pd = __ldg(&g_wdh[bt0 + sdim]);
        ph = __ldg(&g_h[bt0 + sdim]);
    }
    int peid = __ldg(&eids[b * T_]);
    float phh = 0.f;
    if (warp < 4) phh = __ldg(&g_hh[b * T_]);
    __syncthreads();

    for (int t = 0; t < T_; t++) {
        int bt = b * T_ + t;
        if (tid >= 128) { vdh_s[sdim] = pd; h_s[sdim] = ph; }
        int eid = peid;
        float hh = phh;
        __syncthreads();   // S1: staging + prev entsT update visible
        if (t + 1 < T_) {
            if (tid >= 128) {
                size_t bt1 = (size_t)(bt + 1) * H_;
                pd = __ldg(&g_wdh[bt1 + sdim]);
                ph = __ldg(&g_h[bt1 + sdim]);
            }
            peid = __ldg(&eids[bt + 1]);
            if (warp < 4) phh = __ldg(&g_hh[bt + 1]);
        }
        float un = 0.f;
        if (warp < 4) {
            float ev0 = entsT[lane][eid];
            float ev1 = entsT[lane + 32][eid];
            float ev2 = entsT[lane + 64][eid];
            float ev3 = entsT[lane + 96][eid];
            float w0 = vdh_s[lane],      w1 = vdh_s[lane + 32];
            float w2 = vdh_s[lane + 64], w3 = vdh_s[lane + 96];
            float hv0 = h_s[lane],       hv1 = h_s[lane + 32];
            float hv2 = h_s[lane + 64],  hv3 = h_s[lane + 96];
            float dv = ev0 * w0 + ev1 * w1 + ev2 * w2 + ev3 * w3;
            float dh = ev0 * hv0 + ev1 * hv1 + ev2 * hv2 + ev3 * hv3;
#pragma unroll
            for (int o = 16; o; o >>= 1) {
                dv += __shfl_xor_sync(0xffffffffu, dv, o);
                dh += __shfl_xor_sync(0xffffffffu, dh, o);
            }
            float delta = 1.f / (1.f + __expf(-dv));
            float omd = 1.f - delta;
            float n2 = delta * delta + 2.f * delta * omd * dh + omd * omd * hh;
            float rn = rsqrtf(n2);
            float ev_own = (warp == 0) ? ev0 : (warp == 1) ? ev1 : (warp == 2) ? ev2 : ev3;
            float hv_own = (warp == 0) ? hv0 : (warp == 1) ? hv1 : (warp == 2) ? hv2 : hv3;
            un = (delta * ev_own + omd * hv_own) * rn;
        }
        __syncthreads();   // S2: all entsT reads complete before update
        if (warp < 4) {
            entsT[d0][eid] = un;
            g_un[(size_t)bt * H_ + d0] = un;
            g_fsrc[(size_t)bt * H_ + d0] = (eid > 0) ? un : last_r;
            last_r = un;
        }
    }
}

// ---------------- K4b: pred_e, fully parallel gather + dot ----------------
// block = one (b,t); 8 warps x 8 entities; 4 lanes per entity, 32 dims each.
__global__ void __launch_bounds__(256, 4) k_pe(const float* __restrict__ ents0,
                                               float* __restrict__ out_pe) {
    __shared__ __align__(16) float veh[H_];
    int bt = blockIdx.x;
    int b = bt >> 9;
    int tid = threadIdx.x;
    if (tid < H_) veh[tid] = __ldg(&g_weh[(size_t)bt * H_ + tid]);
    __syncthreads();
    int warp = tid >> 5, lane = tid & 31;
    int e = warp * 8 + (lane >> 2);
    int lg = lane & 3;
    int s = __ldg(&g_lut[(size_t)bt * E_ + e]);
    const float4* row = (s >= 0)
        ? reinterpret_cast<const float4*>(g_un + ((size_t)b * T_ + s) * H_)
        : reinterpret_cast<const float4*>(ents0 + ((size_t)b * E_ + e) * H_);
    const float4* veh4 = reinterpret_cast<const float4*>(veh);
    float acc = 0.f;
#pragma unroll
    for (int i = 0; i < 8; i++) {
        float4 u = __ldg(&row[lg * 8 + i]);
        float4 v = veh4[lg * 8 + i];
        acc += u.x * v.x + u.y * v.y + u.z * v.z + u.w * v.w;
    }
    acc += __shfl_xor_sync(0xffffffffu, acc, 1);
    acc += __shfl_xor_sync(0xffffffffu, acc, 2);
    if (lg == 0)
        out_pe[(size_t)bt * E_ + e] = acc + __ldg(&g_exp[(size_t)bt * E_ + e]);
}

// ---------------- K5: ent_feat + z (fp16) ----------------
__global__ void k_feat(const float* __restrict__ WTe, const float* __restrict__ WTc) {
    __shared__ __align__(16) float fs[8][H_];
    int row0 = blockIdx.x * 8;
    int j = threadIdx.x;
    for (int i = j; i < 8 * H_; i += 128)
        fs[i >> 7][i & 127] = g_fsrc[(size_t)row0 * H_ + i];
    __syncthreads();
    float acc_e[8], acc_c[8];
#pragma unroll
    for (int r = 0; r < 8; r++) { acc_e[r] = 0.f; acc_c[r] = 0.f; }
    const float4* we4 = reinterpret_cast<const float4*>(WTe + (size_t)j * H_);
    const float4* wc4 = reinterpret_cast<const float4*>(WTc + (size_t)j * H_);
#pragma unroll 4
    for (int k4 = 0; k4 < H_ / 4; k4++) {
        float4 we = __ldg(we4 + k4);
        float4 wc = __ldg(wc4 + k4);
#pragma unroll
        for (int r = 0; r < 8; r++) {
            float4 f = *reinterpret_cast<const float4*>(&fs[r][k4 * 4]);
            acc_e[r] += we.x * f.x + we.y * f.y + we.z * f.z + we.w * f.w;
            acc_c[r] += wc.x * f.x + wc.y * f.y + wc.z * f.z + wc.w * f.w;
        }
    }
    for (int r = 0; r < 8; r++) {
        int bt = row0 + r;
        float feat = g_sel[bt] ? acc_e[r] : acc_c[r];
        float z = g_h[(size_t)bt * H_ + j] + feat;
        g_z16[(size_t)bt * H_ + j] = __float2half(z);
    }
}

// ---------------- K6: logits = z @ Wx^T + bx, 128x128 tiles ----------------
__global__ void __launch_bounds__(256, 2) k_logits(const float* __restrict__ bx,
                                                   float* __restrict__ out) {
    extern __shared__ __align__(16) __half smemh[];
    __half (*sA)[128] = reinterpret_cast<__half (*)[128]>(smemh);
    __half (*sB)[128] = reinterpret_cast<__half (*)[128]>(smemh + 128 * 128);
    int tid = threadIdx.x;
    int m0 = blockIdx.y * 128;
    int n0 = blockIdx.x * 128;
    {
        int r = tid >> 1;
        int cbase = (tid & 1) * 8;
        const uint4* src = reinterpret_cast<const uint4*>(g_z16) + (size_t)(m0 + r) * 16;
#pragma unroll
        for (int i = 0; i < 8; i++) {
            int c = cbase + i;
            uint4 v = src[c];
            *reinterpret_cast<uint4*>(&sA[r][(c ^ (r & 7)) << 3]) = v;
        }
    }
    {
        int r = tid >> 1;
        int cbase = (tid & 1) * 8;
        int v_ = n0 + r;
        const uint4* src = reinterpret_cast<const uint4*>(g_wx16) + (size_t)v_ * 16;
#pragma unroll
        for (int i = 0; i < 8; i++) {
            int c = cbase + i;
            uint4 v;
            if (v_ < V_) v = src[c];
            else { v.x = 0u; v.y = 0u; v.z = 0u; v.w = 0u; }
            *reinterpret_cast<uint4*>(&sB[r][(c ^ (r & 7)) << 3]) = v;
        }
    }
    __syncthreads();

    int lane = tid & 31, warp = tid >> 5;
    int wm = warp >> 1, wn = warp & 1;
    float acc[2][8][4];
#pragma unroll
    for (int mt = 0; mt < 2; mt++)
#pragma unroll
        for (int nt = 0; nt < 8; nt++)
#pragma unroll
            for (int i = 0; i < 4; i++) acc[mt][nt][i] = 0.f;

#pragma unroll
    for (int ks = 0; ks < 8; ks++) {
        uint32_t afrag[2][4];
#pragma unroll
        for (int mt = 0; mt < 2; mt++) {
            int row = wm * 32 + mt * 16 + (lane & 15);
            int chunk = ks * 2 + (lane >> 4);
            unsigned addr = (unsigned)__cvta_generic_to_shared(&sA[row][(chunk ^ (row & 7)) << 3]);
            asm volatile("ldmatrix.sync.aligned.m8n8.x4.shared.b16 {%0,%1,%2,%3}, [%4];"
                         : "=r"(afrag[mt][0]), "=r"(afrag[mt][1]),
                           "=r"(afrag[mt][2]), "=r"(afrag[mt][3]) : "r"(addr));
        }
        uint32_t bfrag[8][2];
#pragma unroll
        for (int nt = 0; nt < 8; nt++) {
            int row = wn * 64 + nt * 8 + (lane & 7);
            int chunk = ks * 2 + ((lane >> 3) & 1);
            unsigned addr = (unsigned)__cvta_generic_to_shared(&sB[row][(chunk ^ (row & 7)) << 3]);
            asm volatile("ldmatrix.sync.aligned.m8n8.x2.shared.b16 {%0,%1}, [%2];"
                         : "=r"(bfrag[nt][0]), "=r"(bfrag[nt][1]) : "r"(addr));
        }
#pragma unroll
        for (int mt = 0; mt < 2; mt++)
#pragma unroll
            for (int nt = 0; nt < 8; nt++) {
                asm volatile(
                    "mma.sync.aligned.m16n8k16.row.col.f32.f16.f16.f32 "
                    "{%0,%1,%2,%3}, {%4,%5,%6,%7}, {%8,%9}, {%0,%1,%2,%3};"
                    : "+f"(acc[mt][nt][0]), "+f"(acc[mt][nt][1]),
                      "+f"(acc[mt][nt][2]), "+f"(acc[mt][nt][3])
                    : "r"(afrag[mt][0]), "r"(afrag[mt][1]),
                      "r"(afrag[mt][2]), "r"(afrag[mt][3]),
                      "r"(bfrag[nt][0]), "r"(bfrag[nt][1]));
            }
    }
    int rrow = lane >> 2, col = (lane & 3) * 2;
#pragma unroll
    for (int mt = 0; mt < 2; mt++) {
#pragma unroll
        for (int nt = 0; nt < 8; nt++) {
            size_t gm = (size_t)(m0 + wm * 32 + mt * 16 + rrow);
            int gv = n0 + wn * 64 + nt * 8 + col;
            float* a = acc[mt][nt];
            if (gv < V_) {
                float b0 = bx[gv];
                out[gm * V_ + gv]       = a[0] + b0;
                out[(gm + 8) * V_ + gv] = a[2] + b0;
            }
            if (gv + 1 < V_) {
                float b1 = bx[gv + 1];
                out[gm * V_ + gv + 1]       = a[1] + b1;
                out[(gm + 8) * V_ + gv + 1] = a[3] + b1;
            }
        }
    }
}

// ---------------- launch ----------------
extern "C" void kernel_launch(void* const* d_in, const int* in_sizes, int n_in,
                              void* d_out, int out_size) {
    const int*   tokens = (const int*)d_in[0];
    const int*   eids   = (const int*)d_in[1];
    const int*   sids   = (const int*)d_in[2];
    const float* embed  = (const float*)d_in[3];
    const float* Wih    = (const float*)d_in[4];
    const float* Whh    = (const float*)d_in[5];
    const float* bih    = (const float*)d_in[6];
    const float* bhh    = (const float*)d_in[7];
    const float* Wr     = (const float*)d_in[8];
    const float* br     = (const float*)d_in[9];
    const float* We     = (const float*)d_in[10];
    const float* Wd     = (const float*)d_in[11];
    const float* WTe    = (const float*)d_in[12];
    const float* WTc    = (const float*)d_in[13];
    const float* Wx     = (const float*)d_in[14];
    const float* bx     = (const float*)d_in[15];
    const float* ents0  = (const float*)d_in[16];
    const float* lam    = (const float*)d_in[17];
    float* out = (float*)d_out;

    const size_t OFF_R = (size_t)B_ * T_ * V_;
    const size_t OFF_E = OFF_R + (size_t)B_ * T_;

    __half* wx16;
    cudaGetSymbolAddress((void**)&wx16, g_wx16);

    static int attr_set = 0;
    if (!attr_set) {
        cudaFuncSetAttribute(k_logits, cudaFuncAttributeMaxDynamicSharedMemorySize, 65536);
        attr_set = 1;
    }

    int nwx = V_ * H_;
    // k_ent5 at captured launch index 3 for profiling
    k_xw<<<dim3(T_ / 16 + 1, B_), 512>>>(tokens, embed, Wih, bih, bhh,
                                         eids, sids, lam);                  // 0
    k_lstm4<<<1, 512>>>(Whh);                                               // 1
    k_vw<<<(B_ * T_) / 16, 256>>>(We, Wd, Wr, br, out + OFF_R);             // 2
    k_ent5<<<B_, 256>>>(eids, ents0);                                       // 3  <- profiled
    k_pe<<<B_ * T_, 256>>>(ents0, out + OFF_E);                             // 4
    k_cvt<<<(nwx + 255) / 256, 256>>>(Wx, wx16, nwx);                       // 5
    k_feat<<<(B_ * T_) / 8, 128>>>(WTe, WTc);                               // 6
    k_logits<<<dim3((V_ + 127) / 128, (B_ * T_) / 128), 256, 65536>>>(bx, out);  // 7
}